// round 2
// baseline (speedup 1.0000x reference)
#include <cuda_runtime.h>
#include <cuda_bf16.h>
#include <cstdint>

// Problem constants
#define BATCH 2
#define SEQ   8192
#define DMODEL 1024
#define NHEADS 16
#define HDIM  64
#define WIN   128
#define NGLOB 64
#define MROWS (BATCH*SEQ)          // 16384
#define NWIN  (SEQ/WIN)            // 64

// Scratch (allocation-free rule: __device__ globals)
__device__ float g_q[(size_t)MROWS * DMODEL];
__device__ float g_k[(size_t)MROWS * DMODEL];
__device__ float g_v[(size_t)MROWS * DMODEL];
__device__ float g_att[(size_t)MROWS * DMODEL];

// ---------------------------------------------------------------------------
// SGEMM: C[m,n] = sum_k A[m*K+k] * B[n*K+k]   (A row-major [M,K], B row-major [N,K])
// 128x128 block tile, BK=16, 256 threads, 8x8 microtile.
// ---------------------------------------------------------------------------
#define BM 128
#define BN 128
#define BK 16

__global__ __launch_bounds__(256, 2)
void sgemm_nt(const float* __restrict__ A, const float* __restrict__ B,
              float* __restrict__ C, int M, int N, int K)
{
    __shared__ float As[BK][BM + 4];
    __shared__ float Bs[BK][BN + 4];

    const int tid = threadIdx.x;
    const int bm = blockIdx.y * BM;
    const int bn = blockIdx.x * BN;
    const int tx = tid % 16;          // 0..15 -> N direction
    const int ty = tid / 16;          // 0..15 -> M direction

    // load mapping: each thread loads 2 float4 of A and 2 float4 of B per k-step
    const int lr = tid >> 2;          // 0..63
    const int lc = (tid & 3) * 4;     // 0,4,8,12

    float acc[8][8];
#pragma unroll
    for (int i = 0; i < 8; i++)
#pragma unroll
        for (int j = 0; j < 8; j++) acc[i][j] = 0.f;

    for (int k0 = 0; k0 < K; k0 += BK) {
#pragma unroll
        for (int half = 0; half < 2; half++) {
            const int r = lr + half * 64;
            float4 va = *(const float4*)&A[(size_t)(bm + r) * K + k0 + lc];
            As[lc + 0][r] = va.x; As[lc + 1][r] = va.y;
            As[lc + 2][r] = va.z; As[lc + 3][r] = va.w;
            float4 vb = *(const float4*)&B[(size_t)(bn + r) * K + k0 + lc];
            Bs[lc + 0][r] = vb.x; Bs[lc + 1][r] = vb.y;
            Bs[lc + 2][r] = vb.z; Bs[lc + 3][r] = vb.w;
        }
        __syncthreads();

#pragma unroll
        for (int k = 0; k < BK; k++) {
            float4 a0 = *(const float4*)&As[k][ty * 8];
            float4 a1 = *(const float4*)&As[k][ty * 8 + 4];
            float4 b0 = *(const float4*)&Bs[k][tx * 8];
            float4 b1 = *(const float4*)&Bs[k][tx * 8 + 4];
            float a[8] = {a0.x, a0.y, a0.z, a0.w, a1.x, a1.y, a1.z, a1.w};
            float b[8] = {b0.x, b0.y, b0.z, b0.w, b1.x, b1.y, b1.z, b1.w};
#pragma unroll
            for (int i = 0; i < 8; i++)
#pragma unroll
                for (int j = 0; j < 8; j++)
                    acc[i][j] = fmaf(a[i], b[j], acc[i][j]);
        }
        __syncthreads();
    }

#pragma unroll
    for (int i = 0; i < 8; i++) {
        const size_t row = (size_t)(bm + ty * 8 + i) * N + bn + tx * 8;
        float4 o0 = make_float4(acc[i][0], acc[i][1], acc[i][2], acc[i][3]);
        float4 o1 = make_float4(acc[i][4], acc[i][5], acc[i][6], acc[i][7]);
        *(float4*)&C[row]     = o0;
        *(float4*)&C[row + 4] = o1;
    }
}

// ---------------------------------------------------------------------------
// Hybrid attention: one CTA per (window, head, batch). 128 threads = 1 query each.
// Online softmax over 192 key slots: 64 global + 128 local (duplicates for window 0
// are intentional — the reference concatenates them).
// ---------------------------------------------------------------------------
__global__ __launch_bounds__(128)
void attn_kernel(const float* __restrict__ Q, const float* __restrict__ K,
                 const float* __restrict__ V, float* __restrict__ O)
{
    const int win = blockIdx.x;
    const int h   = blockIdx.y;
    const int b   = blockIdx.z;
    const int tid = threadIdx.x;   // query within window

    __shared__ float Ks[64][64];
    __shared__ float Vs[64][64];

    const int qt = win * WIN + tid;
    const size_t qoff = ((size_t)(b * SEQ + qt)) * DMODEL + h * HDIM;

    float q[HDIM];
#pragma unroll
    for (int d = 0; d < HDIM; d++) q[d] = Q[qoff + d];

    float m = -1e30f, l = 0.f;
    float acc[HDIM];
#pragma unroll
    for (int d = 0; d < HDIM; d++) acc[d] = 0.f;

    const int bases[3] = {0, win * WIN, win * WIN + 64};

    for (int c = 0; c < 3; c++) {
        const int tb = bases[c];
        __syncthreads();   // previous chunk fully consumed before overwrite
        // load 64 keys x 64 dims of K and V (float4, coalesced)
        for (int i = tid; i < 64 * 16; i += 128) {
            const int r  = i >> 4;
            const int c4 = (i & 15) * 4;
            const size_t off = ((size_t)(b * SEQ + tb + r)) * DMODEL + h * HDIM + c4;
            *(float4*)&Ks[r][c4] = *(const float4*)&K[off];
            *(float4*)&Vs[r][c4] = *(const float4*)&V[off];
        }
        __syncthreads();

        for (int j = 0; j < 64; j++) {
            float s = 0.f;
#pragma unroll
            for (int d = 0; d < HDIM; d++) s = fmaf(q[d], Ks[j][d], s);
            s *= 0.125f;   // 1/sqrt(64)
            const float mn   = fmaxf(m, s);
            const float corr = __expf(m - mn);
            const float p    = __expf(s - mn);
            l = l * corr + p;
#pragma unroll
            for (int d = 0; d < HDIM; d++)
                acc[d] = fmaf(p, Vs[j][d], acc[d] * corr);
            m = mn;
        }
    }

    const float inv = 1.f / l;
#pragma unroll
    for (int d = 0; d < HDIM; d++) O[qoff + d] = acc[d] * inv;
}

// ---------------------------------------------------------------------------
extern "C" void kernel_launch(void* const* d_in, const int* in_sizes, int n_in,
                              void* d_out, int out_size)
{
    const float* x  = (const float*)d_in[0];
    const float* Wq = (const float*)d_in[1];
    const float* Wk = (const float*)d_in[2];
    const float* Wv = (const float*)d_in[3];
    const float* Wo = (const float*)d_in[4];
    float* out = (float*)d_out;

    float *q, *k, *v, *att;
    cudaGetSymbolAddress((void**)&q,   g_q);
    cudaGetSymbolAddress((void**)&k,   g_k);
    cudaGetSymbolAddress((void**)&v,   g_v);
    cudaGetSymbolAddress((void**)&att, g_att);

    dim3 gg(DMODEL / BN, MROWS / BM);   // (8, 128)
    sgemm_nt<<<gg, 256>>>(x, Wq, q, MROWS, DMODEL, DMODEL);
    sgemm_nt<<<gg, 256>>>(x, Wk, k, MROWS, DMODEL, DMODEL);
    sgemm_nt<<<gg, 256>>>(x, Wv, v, MROWS, DMODEL, DMODEL);

    dim3 ga(NWIN, NHEADS, BATCH);       // (64, 16, 2)
    attn_kernel<<<ga, 128>>>(q, k, v, att);

    sgemm_nt<<<gg, 256>>>(att, Wo, out, MROWS, DMODEL, DMODEL);
}

// round 4
// speedup vs baseline: 2.4382x; 2.4382x over previous
#include <cuda_runtime.h>
#include <cuda_bf16.h>
#include <cstdint>

// ---------------------------------------------------------------------------
// Problem constants
// ---------------------------------------------------------------------------
#define BATCH 2
#define SEQ   8192
#define DMODEL 1024
#define NHEADS 16
#define HDIM  64
#define WIN   128
#define MROWS (BATCH*SEQ)          // 16384
#define NWIN  (SEQ/WIN)            // 64

// ---------------------------------------------------------------------------
// Scratch (allocation-free rule: __device__ globals)
// ---------------------------------------------------------------------------
__device__ float g_q  [(size_t)MROWS * DMODEL];
__device__ float g_k  [(size_t)MROWS * DMODEL];
__device__ float g_v  [(size_t)MROWS * DMODEL];
__device__ float g_att[(size_t)MROWS * DMODEL];
__device__ float g_xr [(size_t)MROWS * DMODEL];
__device__ float g_wq [(size_t)DMODEL * DMODEL];
__device__ float g_wk [(size_t)DMODEL * DMODEL];
__device__ float g_wv [(size_t)DMODEL * DMODEL];
__device__ float g_wo [(size_t)DMODEL * DMODEL];

// ---------------------------------------------------------------------------
// Helpers
// ---------------------------------------------------------------------------
__device__ __forceinline__ uint32_t smem_u32(const void* p) {
    uint32_t a;
    asm("{ .reg .u64 t; cvta.to.shared.u64 t, %1; cvt.u32.u64 %0, t; }" : "=r"(a) : "l"(p));
    return a;
}
__device__ __forceinline__ void cp_async16(uint32_t dst, const void* src) {
    asm volatile("cp.async.cg.shared.global [%0], [%1], 16;" :: "r"(dst), "l"(src));
}
#define CP_COMMIT() asm volatile("cp.async.commit_group;" ::: "memory")
#define CP_WAIT1()  asm volatile("cp.async.wait_group 1;" ::: "memory")
#define CP_WAIT0()  asm volatile("cp.async.wait_group 0;" ::: "memory")

__device__ __forceinline__ float to_tf32(float x) {
    float y;
    asm("cvt.rna.tf32.f32 %0, %1;" : "=f"(y) : "f"(x));
    return y;
}

// m16n8k8 tf32 mma (legacy mma.sync — compiles for plain sm_103, runs on tensor pipe)
__device__ __forceinline__ void mma16x8x8(float* c, const uint32_t* a, const uint32_t* b) {
    asm volatile(
        "mma.sync.aligned.m16n8k8.row.col.f32.tf32.tf32.f32 "
        "{%0,%1,%2,%3}, {%4,%5,%6,%7}, {%8,%9}, {%0,%1,%2,%3};"
        : "+f"(c[0]), "+f"(c[1]), "+f"(c[2]), "+f"(c[3])
        : "r"(a[0]), "r"(a[1]), "r"(a[2]), "r"(a[3]), "r"(b[0]), "r"(b[1]));
}

// ---------------------------------------------------------------------------
// tf32 mma.sync GEMM:  C[m,n] = sum_k A[m,k]*B[n,k]
// A row-major [M,K] (tf32-rounded), B row-major [N,K] (tf32-rounded).
// CTA 128x128, BK=32, 256 threads (8 warps, warp tile 64x32), cp.async 2-stage.
// Smem: padded stride-36 float rows -> conflict-free fragment LDS.
// ---------------------------------------------------------------------------
#define BM 128
#define BN 128
#define BK 32
#define KSTRIDE 36                       // 32 + 4 pad (floats); row = 144B, 16B-aligned
#define TILE_FLOATS (128 * KSTRIDE)      // per A or B tile
#define GEMM_SMEM_BYTES (4 * TILE_FLOATS * 4)   // 2 stages x (A+B) = 73728 B
#define NCH (DMODEL / BK)                // 32

__global__ __launch_bounds__(256, 2)
void gemm_tf32(const float* __restrict__ A, const float* __restrict__ B,
               float* __restrict__ C)
{
    extern __shared__ float sm[];
    float* As[2] = { sm,                   sm + 2 * TILE_FLOATS };
    float* Bs[2] = { sm + TILE_FLOATS,     sm + 3 * TILE_FLOATS };
    const uint32_t smBase = smem_u32(sm);

    const int tid  = threadIdx.x;
    const int wid  = tid >> 5;
    const int lane = tid & 31;
    const int gid  = lane >> 2;      // 0..7
    const int tig  = lane & 3;       // 0..3
    const int moff = (wid & 1) * 64;
    const int noff = (wid >> 1) * 32;
    const int bm   = blockIdx.y * BM;
    const int bn   = blockIdx.x * BN;

    // global->smem mapping: 1024 float4 per tile / 256 thr = 4 each
    const int lrow = tid >> 1;                 // reused below per-iteration
    (void)lrow;

    float acc[4][4][4];
#pragma unroll
    for (int i = 0; i < 4; i++)
#pragma unroll
        for (int j = 0; j < 4; j++)
#pragma unroll
            for (int r = 0; r < 4; r++) acc[i][j][r] = 0.f;

    auto load_chunk = [&](int ch, int s) {
        const int k0 = ch * BK;
        const uint32_t aBase = smBase + (s ? 2u : 0u) * TILE_FLOATS * 4;
        const uint32_t bBase = smBase + (s ? 3u : 1u) * TILE_FLOATS * 4;
#pragma unroll
        for (int i = 0; i < 4; i++) {
            const int c   = tid + i * 256;
            const int row = c >> 3;
            const int col = c & 7;                      // float4 index within row
            cp_async16(aBase + row * (KSTRIDE * 4) + col * 16,
                       A + (size_t)(bm + row) * DMODEL + k0 + col * 4);
            cp_async16(bBase + row * (KSTRIDE * 4) + col * 16,
                       B + (size_t)(bn + row) * DMODEL + k0 + col * 4);
        }
        CP_COMMIT();
    };

    load_chunk(0, 0);

    for (int ch = 0; ch < NCH; ch++) {
        const int s = ch & 1;
        if (ch + 1 < NCH) { load_chunk(ch + 1, s ^ 1); CP_WAIT1(); }
        else              { CP_WAIT0(); }
        __syncthreads();

        const float* Atile = As[s];
        const float* Btile = Bs[s];
#pragma unroll
        for (int kb = 0; kb < BK; kb += 8) {
            uint32_t af[4][4], bf[4][2];
#pragma unroll
            for (int mi = 0; mi < 4; mi++) {
                const int r0 = moff + mi * 16 + gid;
                af[mi][0] = __float_as_uint(Atile[r0 * KSTRIDE + kb + tig]);
                af[mi][1] = __float_as_uint(Atile[(r0 + 8) * KSTRIDE + kb + tig]);
                af[mi][2] = __float_as_uint(Atile[r0 * KSTRIDE + kb + tig + 4]);
                af[mi][3] = __float_as_uint(Atile[(r0 + 8) * KSTRIDE + kb + tig + 4]);
            }
#pragma unroll
            for (int ni = 0; ni < 4; ni++) {
                const int r0 = noff + ni * 8 + gid;
                bf[ni][0] = __float_as_uint(Btile[r0 * KSTRIDE + kb + tig]);
                bf[ni][1] = __float_as_uint(Btile[r0 * KSTRIDE + kb + tig + 4]);
            }
#pragma unroll
            for (int mi = 0; mi < 4; mi++)
#pragma unroll
                for (int ni = 0; ni < 4; ni++)
                    mma16x8x8(acc[mi][ni], af[mi], bf[ni]);
        }
        __syncthreads();
    }

    // epilogue: float2 stores
#pragma unroll
    for (int mi = 0; mi < 4; mi++) {
#pragma unroll
        for (int ni = 0; ni < 4; ni++) {
            const int row0 = bm + moff + mi * 16 + gid;
            const int col0 = bn + noff + ni * 8 + 2 * tig;
            *(float2*)&C[(size_t)row0 * DMODEL + col0] =
                make_float2(acc[mi][ni][0], acc[mi][ni][1]);
            *(float2*)&C[(size_t)(row0 + 8) * DMODEL + col0] =
                make_float2(acc[mi][ni][2], acc[mi][ni][3]);
        }
    }
}

// ---------------------------------------------------------------------------
// tf32 rounding prep
// ---------------------------------------------------------------------------
__global__ void round_tf32_kernel(const float* __restrict__ in, float* __restrict__ out, int n4)
{
    for (int i = blockIdx.x * blockDim.x + threadIdx.x; i < n4; i += gridDim.x * blockDim.x) {
        float4 v = ((const float4*)in)[i];
        v.x = to_tf32(v.x); v.y = to_tf32(v.y); v.z = to_tf32(v.z); v.w = to_tf32(v.w);
        ((float4*)out)[i] = v;
    }
}

// ---------------------------------------------------------------------------
// Hybrid attention: one CTA per (window, head, batch), 128 threads = 1 query.
// Chunked keys (3 x 64), group-of-8 softmax rescale, float4 smem, 4-way ILP dots.
// Output rounded to tf32 (feeds the Wo tensor GEMM).
// ---------------------------------------------------------------------------
__global__ __launch_bounds__(128)
void attn_kernel(const float* __restrict__ Q, const float* __restrict__ K,
                 const float* __restrict__ V, float* __restrict__ O)
{
    const int win = blockIdx.x;
    const int h   = blockIdx.y;
    const int b   = blockIdx.z;
    const int tid = threadIdx.x;

    __shared__ float4 Ks[64][16];
    __shared__ float4 Vs[64][16];

    const int qt = win * WIN + tid;
    const size_t qvec = (size_t)(b * SEQ + qt) * (DMODEL / 4) + h * (HDIM / 4);

    float4 q4[16];
#pragma unroll
    for (int i = 0; i < 16; i++) {
        float4 v = ((const float4*)Q)[qvec + i];
        v.x *= 0.125f; v.y *= 0.125f; v.z *= 0.125f; v.w *= 0.125f;   // fold 1/sqrt(64)
        q4[i] = v;
    }

    float m = -1e30f, l = 0.f;
    float4 acc[16];
#pragma unroll
    for (int i = 0; i < 16; i++) acc[i] = make_float4(0.f, 0.f, 0.f, 0.f);

    const int bases[3] = {0, win * WIN, win * WIN + 64};

    for (int c = 0; c < 3; c++) {
        const int tb = bases[c];
        __syncthreads();
        for (int i = tid; i < 64 * 16; i += 128) {
            const int r  = i >> 4;
            const int c4 = i & 15;
            const size_t off = (size_t)(b * SEQ + tb + r) * (DMODEL / 4) + h * (HDIM / 4) + c4;
            Ks[r][c4] = ((const float4*)K)[off];
            Vs[r][c4] = ((const float4*)V)[off];
        }
        __syncthreads();

        for (int g = 0; g < 8; g++) {
            float s[8];
#pragma unroll
            for (int j = 0; j < 8; j++) {
                const int kk = g * 8 + j;
                float a0 = 0.f, a1 = 0.f, a2 = 0.f, a3 = 0.f;
#pragma unroll
                for (int d = 0; d < 16; d++) {
                    float4 kv = Ks[kk][d];
                    a0 = fmaf(q4[d].x, kv.x, a0);
                    a1 = fmaf(q4[d].y, kv.y, a1);
                    a2 = fmaf(q4[d].z, kv.z, a2);
                    a3 = fmaf(q4[d].w, kv.w, a3);
                }
                s[j] = (a0 + a1) + (a2 + a3);
            }
            float gm = s[0];
#pragma unroll
            for (int j = 1; j < 8; j++) gm = fmaxf(gm, s[j]);
            const float mn   = fmaxf(m, gm);
            const float corr = __expf(m - mn);
            m = mn;
            l *= corr;
#pragma unroll
            for (int d = 0; d < 16; d++) {
                acc[d].x *= corr; acc[d].y *= corr; acc[d].z *= corr; acc[d].w *= corr;
            }
#pragma unroll
            for (int j = 0; j < 8; j++) {
                const int kk = g * 8 + j;
                const float p = __expf(s[j] - mn);
                l += p;
#pragma unroll
                for (int d = 0; d < 16; d++) {
                    float4 vv = Vs[kk][d];
                    acc[d].x = fmaf(p, vv.x, acc[d].x);
                    acc[d].y = fmaf(p, vv.y, acc[d].y);
                    acc[d].z = fmaf(p, vv.z, acc[d].z);
                    acc[d].w = fmaf(p, vv.w, acc[d].w);
                }
            }
        }
    }

    const float inv = 1.f / l;
#pragma unroll
    for (int d = 0; d < 16; d++) {
        float4 o;
        o.x = to_tf32(acc[d].x * inv);
        o.y = to_tf32(acc[d].y * inv);
        o.z = to_tf32(acc[d].z * inv);
        o.w = to_tf32(acc[d].w * inv);
        ((float4*)O)[qvec + d] = o;
    }
}

// ---------------------------------------------------------------------------
extern "C" void kernel_launch(void* const* d_in, const int* in_sizes, int n_in,
                              void* d_out, int out_size)
{
    const float* x  = (const float*)d_in[0];
    const float* Wq = (const float*)d_in[1];
    const float* Wk = (const float*)d_in[2];
    const float* Wv = (const float*)d_in[3];
    const float* Wo = (const float*)d_in[4];
    float* out = (float*)d_out;

    float *q, *k, *v, *att, *xr, *wq, *wk, *wv, *wo;
    cudaGetSymbolAddress((void**)&q,   g_q);
    cudaGetSymbolAddress((void**)&k,   g_k);
    cudaGetSymbolAddress((void**)&v,   g_v);
    cudaGetSymbolAddress((void**)&att, g_att);
    cudaGetSymbolAddress((void**)&xr,  g_xr);
    cudaGetSymbolAddress((void**)&wq,  g_wq);
    cudaGetSymbolAddress((void**)&wk,  g_wk);
    cudaGetSymbolAddress((void**)&wv,  g_wv);
    cudaGetSymbolAddress((void**)&wo,  g_wo);

    cudaFuncSetAttribute(gemm_tf32, cudaFuncAttributeMaxDynamicSharedMemorySize,
                         GEMM_SMEM_BYTES);

    // tf32-round GEMM inputs
    round_tf32_kernel<<<2048, 256>>>(x,  xr, MROWS * DMODEL / 4);
    round_tf32_kernel<<<512,  256>>>(Wq, wq, DMODEL * DMODEL / 4);
    round_tf32_kernel<<<512,  256>>>(Wk, wk, DMODEL * DMODEL / 4);
    round_tf32_kernel<<<512,  256>>>(Wv, wv, DMODEL * DMODEL / 4);
    round_tf32_kernel<<<512,  256>>>(Wo, wo, DMODEL * DMODEL / 4);

    dim3 gg(DMODEL / BN, MROWS / BM);   // (8, 128)
    gemm_tf32<<<gg, 256, GEMM_SMEM_BYTES>>>(xr, wq, q);
    gemm_tf32<<<gg, 256, GEMM_SMEM_BYTES>>>(xr, wk, k);
    gemm_tf32<<<gg, 256, GEMM_SMEM_BYTES>>>(xr, wv, v);

    dim3 ga(NWIN, NHEADS, BATCH);       // (64, 16, 2)
    attn_kernel<<<ga, 128>>>(q, k, v, att);

    gemm_tf32<<<gg, 256, GEMM_SMEM_BYTES>>>(att, wo, out);
}

// round 5
// speedup vs baseline: 2.9054x; 1.1916x over previous
#include <cuda_runtime.h>
#include <cuda_bf16.h>
#include <cstdint>

// ---------------------------------------------------------------------------
// Problem constants
// ---------------------------------------------------------------------------
#define BATCH 2
#define SEQ   8192
#define DMODEL 1024
#define NHEADS 16
#define HDIM  64
#define WIN   128
#define MROWS (BATCH*SEQ)          // 16384
#define NWIN  (SEQ/WIN)            // 64

// ---------------------------------------------------------------------------
// Scratch (allocation-free rule: __device__ globals)
// ---------------------------------------------------------------------------
__device__ float g_q  [(size_t)MROWS * DMODEL];
__device__ float g_k  [(size_t)MROWS * DMODEL];
__device__ float g_v  [(size_t)MROWS * DMODEL];
__device__ float g_att[(size_t)MROWS * DMODEL];
__device__ float g_xr [(size_t)MROWS * DMODEL];
__device__ float g_wq [(size_t)DMODEL * DMODEL];
__device__ float g_wk [(size_t)DMODEL * DMODEL];
__device__ float g_wv [(size_t)DMODEL * DMODEL];
__device__ float g_wo [(size_t)DMODEL * DMODEL];

// ---------------------------------------------------------------------------
// Helpers
// ---------------------------------------------------------------------------
__device__ __forceinline__ uint32_t smem_u32(const void* p) {
    uint32_t a;
    asm("{ .reg .u64 t; cvta.to.shared.u64 t, %1; cvt.u32.u64 %0, t; }" : "=r"(a) : "l"(p));
    return a;
}
__device__ __forceinline__ void cp_async16(uint32_t dst, const void* src) {
    asm volatile("cp.async.cg.shared.global [%0], [%1], 16;" :: "r"(dst), "l"(src));
}
#define CP_COMMIT() asm volatile("cp.async.commit_group;" ::: "memory")
#define CP_WAIT1()  asm volatile("cp.async.wait_group 1;" ::: "memory")
#define CP_WAIT0()  asm volatile("cp.async.wait_group 0;" ::: "memory")

__device__ __forceinline__ float to_tf32(float x) {
    float y;
    asm("cvt.rna.tf32.f32 %0, %1;" : "=f"(y) : "f"(x));
    return y;
}

// m16n8k8 tf32 mma (legacy mma.sync — compiles for plain sm_103, tensor pipe)
__device__ __forceinline__ void mma16x8x8(float* c, const uint32_t* a, const uint32_t* b) {
    asm volatile(
        "mma.sync.aligned.m16n8k8.row.col.f32.tf32.tf32.f32 "
        "{%0,%1,%2,%3}, {%4,%5,%6,%7}, {%8,%9}, {%0,%1,%2,%3};"
        : "+f"(c[0]), "+f"(c[1]), "+f"(c[2]), "+f"(c[3])
        : "r"(a[0]), "r"(a[1]), "r"(a[2]), "r"(a[3]), "r"(b[0]), "r"(b[1]));
}

// ldmatrix x4: 4 8x8 b16 matrices, per-lane row addresses
__device__ __forceinline__ void ldsm_x4(uint32_t* r, uint32_t addr) {
    asm volatile("ldmatrix.sync.aligned.m8n8.x4.shared.b16 {%0,%1,%2,%3}, [%4];"
                 : "=r"(r[0]), "=r"(r[1]), "=r"(r[2]), "=r"(r[3]) : "r"(addr));
}

// ---------------------------------------------------------------------------
// tf32 mma.sync GEMM:  C[m,n] = sum_k A[m,k]*B[n,k]
// CTA 128x128, BK=32, 256 threads (8 warps, warp tile 64x32), cp.async 2-stage.
// Fragment feed via ldmatrix.x4 (6 per kb-step instead of 24 scalar LDS).
// blockIdx.z selects one of up to 3 (B, C) pairs (fused QKV projection).
// ---------------------------------------------------------------------------
#define BM 128
#define BN 128
#define BK 32
#define KSTRIDE 36                       // 32 + 4 pad floats; row = 144B (16B-aligned)
#define TILE_FLOATS (128 * KSTRIDE)
#define STAGE_BYTES (2 * TILE_FLOATS * 4)        // A+B one stage
#define GEMM_SMEM_BYTES (2 * STAGE_BYTES)        // 73728 B
#define NCH (DMODEL / BK)                // 32

__global__ __launch_bounds__(256, 2)
void gemm_tf32(const float* __restrict__ A,
               const float* __restrict__ B0, const float* __restrict__ B1,
               const float* __restrict__ B2,
               float* __restrict__ C0, float* __restrict__ C1, float* __restrict__ C2)
{
    const float* B = (blockIdx.z == 0) ? B0 : (blockIdx.z == 1) ? B1 : B2;
    float*       C = (blockIdx.z == 0) ? C0 : (blockIdx.z == 1) ? C1 : C2;

    extern __shared__ float sm[];
    const uint32_t smBase = smem_u32(sm);

    const int tid  = threadIdx.x;
    const int wid  = tid >> 5;
    const int lane = tid & 31;
    const int gid  = lane >> 2;      // 0..7
    const int tig  = lane & 3;       // 0..3
    const int moff = (wid & 1) * 64;
    const int noff = (wid >> 1) * 32;
    const int bm   = blockIdx.y * BM;
    const int bn   = blockIdx.x * BN;

    // ldmatrix per-lane base addresses (stage 0, kb = 0), byte offsets
    // A frag mi: matrices {rows gid | k 0..3}, {rows gid+8 | k 0..3},
    //            {rows gid | k 4..7}, {rows gid+8 | k 4..7}
    uint32_t aAddr[4], bAddr[2];
#pragma unroll
    for (int mi = 0; mi < 4; mi++) {
        const int arow = moff + mi * 16 + (lane & 15);
        const int acol = (lane & 16) ? 4 : 0;
        aAddr[mi] = smBase + (uint32_t)(arow * KSTRIDE + acol) * 4u;
    }
    // B frag pair p covers ni=2p,2p+1: matrices {rows(2p) | k0}, {rows(2p) | k4},
    //                                           {rows(2p+1) | k0}, {rows(2p+1) | k4}
#pragma unroll
    for (int p = 0; p < 2; p++) {
        const int nrow = noff + (2 * p + ((lane >> 4) & 1)) * 8 + (lane & 7);
        const int ncol = (lane & 8) ? 4 : 0;
        bAddr[p] = smBase + (uint32_t)(TILE_FLOATS + nrow * KSTRIDE + ncol) * 4u;
    }

    float acc[4][4][4];
#pragma unroll
    for (int i = 0; i < 4; i++)
#pragma unroll
        for (int j = 0; j < 4; j++)
#pragma unroll
            for (int r = 0; r < 4; r++) acc[i][j][r] = 0.f;

    auto load_chunk = [&](int ch, int s) {
        const int k0 = ch * BK;
        const uint32_t aBase = smBase + (uint32_t)s * STAGE_BYTES;
        const uint32_t bBase = aBase + TILE_FLOATS * 4u;
#pragma unroll
        for (int i = 0; i < 4; i++) {
            const int c   = tid + i * 256;
            const int row = c >> 3;
            const int col = c & 7;
            cp_async16(aBase + row * (KSTRIDE * 4) + col * 16,
                       A + (size_t)(bm + row) * DMODEL + k0 + col * 4);
            cp_async16(bBase + row * (KSTRIDE * 4) + col * 16,
                       B + (size_t)(bn + row) * DMODEL + k0 + col * 4);
        }
        CP_COMMIT();
    };

    load_chunk(0, 0);

    for (int ch = 0; ch < NCH; ch++) {
        const int s = ch & 1;
        if (ch + 1 < NCH) { load_chunk(ch + 1, s ^ 1); CP_WAIT1(); }
        else              { CP_WAIT0(); }
        __syncthreads();

        const uint32_t soff = (uint32_t)s * STAGE_BYTES;
#pragma unroll
        for (int kb8 = 0; kb8 < 4; kb8++) {
            const uint32_t kOff = soff + kb8 * 32u;   // 8 floats per kb-step
            uint32_t af[4][4], bf[2][4];
#pragma unroll
            for (int mi = 0; mi < 4; mi++) ldsm_x4(af[mi], aAddr[mi] + kOff);
#pragma unroll
            for (int p = 0; p < 2; p++)    ldsm_x4(bf[p],  bAddr[p] + kOff);
#pragma unroll
            for (int mi = 0; mi < 4; mi++)
#pragma unroll
                for (int ni = 0; ni < 4; ni++)
                    mma16x8x8(acc[mi][ni], af[mi], &bf[ni >> 1][(ni & 1) * 2]);
        }
        __syncthreads();
    }

    // epilogue: float2 stores
#pragma unroll
    for (int mi = 0; mi < 4; mi++) {
#pragma unroll
        for (int ni = 0; ni < 4; ni++) {
            const int row0 = bm + moff + mi * 16 + gid;
            const int col0 = bn + noff + ni * 8 + 2 * tig;
            *(float2*)&C[(size_t)row0 * DMODEL + col0] =
                make_float2(acc[mi][ni][0], acc[mi][ni][1]);
            *(float2*)&C[(size_t)(row0 + 8) * DMODEL + col0] =
                make_float2(acc[mi][ni][2], acc[mi][ni][3]);
        }
    }
}

// ---------------------------------------------------------------------------
// tf32 rounding prep
// ---------------------------------------------------------------------------
__global__ void round_tf32_kernel(const float* __restrict__ in, float* __restrict__ out, int n4)
{
    for (int i = blockIdx.x * blockDim.x + threadIdx.x; i < n4; i += gridDim.x * blockDim.x) {
        float4 v = ((const float4*)in)[i];
        v.x = to_tf32(v.x); v.y = to_tf32(v.y); v.z = to_tf32(v.z); v.w = to_tf32(v.w);
        ((float4*)out)[i] = v;
    }
}

// ---------------------------------------------------------------------------
// Hybrid attention: one CTA per (window, head, batch), 128 threads = 1 query.
// ---------------------------------------------------------------------------
__global__ __launch_bounds__(128)
void attn_kernel(const float* __restrict__ Q, const float* __restrict__ K,
                 const float* __restrict__ V, float* __restrict__ O)
{
    const int win = blockIdx.x;
    const int h   = blockIdx.y;
    const int b   = blockIdx.z;
    const int tid = threadIdx.x;

    __shared__ float4 Ks[64][16];
    __shared__ float4 Vs[64][16];

    const int qt = win * WIN + tid;
    const size_t qvec = (size_t)(b * SEQ + qt) * (DMODEL / 4) + h * (HDIM / 4);

    float4 q4[16];
#pragma unroll
    for (int i = 0; i < 16; i++) {
        float4 v = ((const float4*)Q)[qvec + i];
        v.x *= 0.125f; v.y *= 0.125f; v.z *= 0.125f; v.w *= 0.125f;   // fold 1/sqrt(64)
        q4[i] = v;
    }

    float m = -1e30f, l = 0.f;
    float4 acc[16];
#pragma unroll
    for (int i = 0; i < 16; i++) acc[i] = make_float4(0.f, 0.f, 0.f, 0.f);

    const int bases[3] = {0, win * WIN, win * WIN + 64};

    for (int c = 0; c < 3; c++) {
        const int tb = bases[c];
        __syncthreads();
        for (int i = tid; i < 64 * 16; i += 128) {
            const int r  = i >> 4;
            const int c4 = i & 15;
            const size_t off = (size_t)(b * SEQ + tb + r) * (DMODEL / 4) + h * (HDIM / 4) + c4;
            Ks[r][c4] = ((const float4*)K)[off];
            Vs[r][c4] = ((const float4*)V)[off];
        }
        __syncthreads();

        for (int g = 0; g < 8; g++) {
            float s[8];
#pragma unroll
            for (int j = 0; j < 8; j++) {
                const int kk = g * 8 + j;
                float a0 = 0.f, a1 = 0.f, a2 = 0.f, a3 = 0.f;
#pragma unroll
                for (int d = 0; d < 16; d++) {
                    float4 kv = Ks[kk][d];
                    a0 = fmaf(q4[d].x, kv.x, a0);
                    a1 = fmaf(q4[d].y, kv.y, a1);
                    a2 = fmaf(q4[d].z, kv.z, a2);
                    a3 = fmaf(q4[d].w, kv.w, a3);
                }
                s[j] = (a0 + a1) + (a2 + a3);
            }
            float gm = s[0];
#pragma unroll
            for (int j = 1; j < 8; j++) gm = fmaxf(gm, s[j]);
            const float mn   = fmaxf(m, gm);
            const float corr = __expf(m - mn);
            m = mn;
            l *= corr;
#pragma unroll
            for (int d = 0; d < 16; d++) {
                acc[d].x *= corr; acc[d].y *= corr; acc[d].z *= corr; acc[d].w *= corr;
            }
#pragma unroll
            for (int j = 0; j < 8; j++) {
                const int kk = g * 8 + j;
                const float p = __expf(s[j] - mn);
                l += p;
#pragma unroll
                for (int d = 0; d < 16; d++) {
                    float4 vv = Vs[kk][d];
                    acc[d].x = fmaf(p, vv.x, acc[d].x);
                    acc[d].y = fmaf(p, vv.y, acc[d].y);
                    acc[d].z = fmaf(p, vv.z, acc[d].z);
                    acc[d].w = fmaf(p, vv.w, acc[d].w);
                }
            }
        }
    }

    const float inv = 1.f / l;
#pragma unroll
    for (int d = 0; d < 16; d++) {
        float4 o;
        o.x = to_tf32(acc[d].x * inv);
        o.y = to_tf32(acc[d].y * inv);
        o.z = to_tf32(acc[d].z * inv);
        o.w = to_tf32(acc[d].w * inv);
        ((float4*)O)[qvec + d] = o;
    }
}

// ---------------------------------------------------------------------------
extern "C" void kernel_launch(void* const* d_in, const int* in_sizes, int n_in,
                              void* d_out, int out_size)
{
    const float* x  = (const float*)d_in[0];
    const float* Wq = (const float*)d_in[1];
    const float* Wk = (const float*)d_in[2];
    const float* Wv = (const float*)d_in[3];
    const float* Wo = (const float*)d_in[4];
    float* out = (float*)d_out;

    float *q, *k, *v, *att, *xr, *wq, *wk, *wv, *wo;
    cudaGetSymbolAddress((void**)&q,   g_q);
    cudaGetSymbolAddress((void**)&k,   g_k);
    cudaGetSymbolAddress((void**)&v,   g_v);
    cudaGetSymbolAddress((void**)&att, g_att);
    cudaGetSymbolAddress((void**)&xr,  g_xr);
    cudaGetSymbolAddress((void**)&wq,  g_wq);
    cudaGetSymbolAddress((void**)&wk,  g_wk);
    cudaGetSymbolAddress((void**)&wv,  g_wv);
    cudaGetSymbolAddress((void**)&wo,  g_wo);

    cudaFuncSetAttribute(gemm_tf32, cudaFuncAttributeMaxDynamicSharedMemorySize,
                         GEMM_SMEM_BYTES);

    // tf32-round GEMM inputs
    round_tf32_kernel<<<2048, 256>>>(x,  xr, MROWS * DMODEL / 4);
    round_tf32_kernel<<<512,  256>>>(Wq, wq, DMODEL * DMODEL / 4);
    round_tf32_kernel<<<512,  256>>>(Wk, wk, DMODEL * DMODEL / 4);
    round_tf32_kernel<<<512,  256>>>(Wv, wv, DMODEL * DMODEL / 4);
    round_tf32_kernel<<<512,  256>>>(Wo, wo, DMODEL * DMODEL / 4);

    // fused QKV projection: grid.z picks (W, out) pair
    dim3 gqkv(DMODEL / BN, MROWS / BM, 3);   // (8, 128, 3)
    gemm_tf32<<<gqkv, 256, GEMM_SMEM_BYTES>>>(xr, wq, wk, wv, q, k, v);

    dim3 ga(NWIN, NHEADS, BATCH);            // (64, 16, 2)
    attn_kernel<<<ga, 128>>>(q, k, v, att);

    dim3 go(DMODEL / BN, MROWS / BM, 1);     // (8, 128, 1)
    gemm_tf32<<<go, 256, GEMM_SMEM_BYTES>>>(att, wo, wo, wo, out, out, out);
}

// round 7
// speedup vs baseline: 4.0341x; 1.3885x over previous
#include <cuda_runtime.h>
#include <cuda_bf16.h>
#include <cstdint>

// ---------------------------------------------------------------------------
// Problem constants
// ---------------------------------------------------------------------------
#define BATCH 2
#define SEQ   8192
#define DMODEL 1024
#define NHEADS 16
#define HDIM  64
#define WIN   128
#define MROWS (BATCH*SEQ)          // 16384
#define NWIN  (SEQ/WIN)            // 64

// ---------------------------------------------------------------------------
// Scratch (allocation-free rule: __device__ globals)
// ---------------------------------------------------------------------------
__device__ float g_q  [(size_t)MROWS * DMODEL];
__device__ float g_k  [(size_t)MROWS * DMODEL];
__device__ float g_v  [(size_t)MROWS * DMODEL];
__device__ float g_att[(size_t)MROWS * DMODEL];
__device__ float g_xr [(size_t)MROWS * DMODEL];
__device__ float g_wq [(size_t)DMODEL * DMODEL];
__device__ float g_wk [(size_t)DMODEL * DMODEL];
__device__ float g_wv [(size_t)DMODEL * DMODEL];
__device__ float g_wo [(size_t)DMODEL * DMODEL];

// ---------------------------------------------------------------------------
// Helpers
// ---------------------------------------------------------------------------
__device__ __forceinline__ uint32_t smem_u32(const void* p) {
    uint32_t a;
    asm("{ .reg .u64 t; cvta.to.shared.u64 t, %1; cvt.u32.u64 %0, t; }" : "=r"(a) : "l"(p));
    return a;
}
__device__ __forceinline__ void cp_async16(uint32_t dst, const void* src) {
    asm volatile("cp.async.cg.shared.global [%0], [%1], 16;" :: "r"(dst), "l"(src));
}
#define CP_COMMIT() asm volatile("cp.async.commit_group;" ::: "memory")
#define CP_WAIT1()  asm volatile("cp.async.wait_group 1;" ::: "memory")
#define CP_WAIT0()  asm volatile("cp.async.wait_group 0;" ::: "memory")

__device__ __forceinline__ float to_tf32(float x) {
    float y;
    asm("cvt.rna.tf32.f32 %0, %1;" : "=f"(y) : "f"(x));
    return y;
}

// m16n8k8 tf32 mma (legacy mma.sync — compiles for plain sm_103, tensor pipe)
__device__ __forceinline__ void mma16x8x8(float* c, const uint32_t* a, const uint32_t* b) {
    asm volatile(
        "mma.sync.aligned.m16n8k8.row.col.f32.tf32.tf32.f32 "
        "{%0,%1,%2,%3}, {%4,%5,%6,%7}, {%8,%9}, {%0,%1,%2,%3};"
        : "+f"(c[0]), "+f"(c[1]), "+f"(c[2]), "+f"(c[3])
        : "r"(a[0]), "r"(a[1]), "r"(a[2]), "r"(a[3]), "r"(b[0]), "r"(b[1]));
}

// ldmatrix x4: 4 8x8 b16 matrices, per-lane row addresses
__device__ __forceinline__ void ldsm_x4(uint32_t* r, uint32_t addr) {
    asm volatile("ldmatrix.sync.aligned.m8n8.x4.shared.b16 {%0,%1,%2,%3}, [%4];"
                 : "=r"(r[0]), "=r"(r[1]), "=r"(r[2]), "=r"(r[3]) : "r"(addr));
}

// ---------------------------------------------------------------------------
// tf32 mma.sync GEMM:  C[m,n] = sum_k A[m,k]*B[n,k]
// CTA 128x128, BK=32, 256 threads (8 warps, warp tile 64x32), cp.async 2-stage.
// blockIdx.z selects one of up to 3 (B, C) pairs (fused QKV projection).
// roundOut: round outputs to tf32 (for tensors feeding later tensor-core mma).
// ---------------------------------------------------------------------------
#define BM 128
#define BN 128
#define BK 32
#define KSTRIDE 36                       // 32 + 4 pad floats; row = 144B (16B-aligned)
#define TILE_FLOATS (128 * KSTRIDE)
#define STAGE_BYTES (2 * TILE_FLOATS * 4)        // A+B one stage
#define GEMM_SMEM_BYTES (2 * STAGE_BYTES)        // 73728 B
#define NCH (DMODEL / BK)                // 32

__global__ __launch_bounds__(256, 2)
void gemm_tf32(const float* __restrict__ A,
               const float* __restrict__ B0, const float* __restrict__ B1,
               const float* __restrict__ B2,
               float* __restrict__ C0, float* __restrict__ C1, float* __restrict__ C2,
               int roundOut)
{
    const float* B = (blockIdx.z == 0) ? B0 : (blockIdx.z == 1) ? B1 : B2;
    float*       C = (blockIdx.z == 0) ? C0 : (blockIdx.z == 1) ? C1 : C2;

    extern __shared__ float sm[];
    const uint32_t smBase = smem_u32(sm);

    const int tid  = threadIdx.x;
    const int wid  = tid >> 5;
    const int lane = tid & 31;
    const int gid  = lane >> 2;      // 0..7
    const int tig  = lane & 3;       // 0..3
    const int moff = (wid & 1) * 64;
    const int noff = (wid >> 1) * 32;
    const int bm   = blockIdx.y * BM;
    const int bn   = blockIdx.x * BN;

    uint32_t aAddr[4], bAddr[2];
#pragma unroll
    for (int mi = 0; mi < 4; mi++) {
        const int arow = moff + mi * 16 + (lane & 15);
        const int acol = (lane & 16) ? 4 : 0;
        aAddr[mi] = smBase + (uint32_t)(arow * KSTRIDE + acol) * 4u;
    }
#pragma unroll
    for (int p = 0; p < 2; p++) {
        const int nrow = noff + (2 * p + ((lane >> 4) & 1)) * 8 + (lane & 7);
        const int ncol = (lane & 8) ? 4 : 0;
        bAddr[p] = smBase + (uint32_t)(TILE_FLOATS + nrow * KSTRIDE + ncol) * 4u;
    }

    float acc[4][4][4];
#pragma unroll
    for (int i = 0; i < 4; i++)
#pragma unroll
        for (int j = 0; j < 4; j++)
#pragma unroll
            for (int r = 0; r < 4; r++) acc[i][j][r] = 0.f;

    auto load_chunk = [&](int ch, int s) {
        const int k0 = ch * BK;
        const uint32_t aBase = smBase + (uint32_t)s * STAGE_BYTES;
        const uint32_t bBase = aBase + TILE_FLOATS * 4u;
#pragma unroll
        for (int i = 0; i < 4; i++) {
            const int c   = tid + i * 256;
            const int row = c >> 3;
            const int col = c & 7;
            cp_async16(aBase + row * (KSTRIDE * 4) + col * 16,
                       A + (size_t)(bm + row) * DMODEL + k0 + col * 4);
            cp_async16(bBase + row * (KSTRIDE * 4) + col * 16,
                       B + (size_t)(bn + row) * DMODEL + k0 + col * 4);
        }
        CP_COMMIT();
    };

    load_chunk(0, 0);

    for (int ch = 0; ch < NCH; ch++) {
        const int s = ch & 1;
        if (ch + 1 < NCH) { load_chunk(ch + 1, s ^ 1); CP_WAIT1(); }
        else              { CP_WAIT0(); }
        __syncthreads();

        const uint32_t soff = (uint32_t)s * STAGE_BYTES;
#pragma unroll
        for (int kb8 = 0; kb8 < 4; kb8++) {
            const uint32_t kOff = soff + kb8 * 32u;   // 8 floats per kb-step
            uint32_t af[4][4], bf[2][4];
#pragma unroll
            for (int mi = 0; mi < 4; mi++) ldsm_x4(af[mi], aAddr[mi] + kOff);
#pragma unroll
            for (int p = 0; p < 2; p++)    ldsm_x4(bf[p],  bAddr[p] + kOff);
#pragma unroll
            for (int mi = 0; mi < 4; mi++)
#pragma unroll
                for (int ni = 0; ni < 4; ni++)
                    mma16x8x8(acc[mi][ni], af[mi], &bf[ni >> 1][(ni & 1) * 2]);
        }
        __syncthreads();
    }

    // epilogue: float2 stores (optionally tf32-rounded for downstream mma use)
#pragma unroll
    for (int mi = 0; mi < 4; mi++) {
#pragma unroll
        for (int ni = 0; ni < 4; ni++) {
            const int row0 = bm + moff + mi * 16 + gid;
            const int col0 = bn + noff + ni * 8 + 2 * tig;
            float v0 = acc[mi][ni][0], v1 = acc[mi][ni][1];
            float v2 = acc[mi][ni][2], v3 = acc[mi][ni][3];
            if (roundOut) {
                v0 = to_tf32(v0); v1 = to_tf32(v1);
                v2 = to_tf32(v2); v3 = to_tf32(v3);
            }
            *(float2*)&C[(size_t)row0 * DMODEL + col0]       = make_float2(v0, v1);
            *(float2*)&C[(size_t)(row0 + 8) * DMODEL + col0] = make_float2(v2, v3);
        }
    }
}

// ---------------------------------------------------------------------------
// tf32 rounding prep
// ---------------------------------------------------------------------------
__global__ void round_tf32_kernel(const float* __restrict__ in, float* __restrict__ out, int n4)
{
    for (int i = blockIdx.x * blockDim.x + threadIdx.x; i < n4; i += gridDim.x * blockDim.x) {
        float4 v = ((const float4*)in)[i];
        v.x = to_tf32(v.x); v.y = to_tf32(v.y); v.z = to_tf32(v.z); v.w = to_tf32(v.w);
        ((float4*)out)[i] = v;
    }
}

// ---------------------------------------------------------------------------
// Tensor-core hybrid attention.
// One CTA per (window, head, batch); 256 threads = 8 warps, warp w owns 16 query
// rows. All 192 keys (64 global + 128 local; window-0 duplication intentional)
// staged in smem. S = Q K^T via mma (tf32), exact single-pass softmax in
// registers, P converted to A-frags via quad shuffles, O = P V via mma.
// Smem strides: Q/K 68 floats (ldmatrix conflict-free: bank 4r), V 72 floats
// (scalar b-frag LDS conflict-free: bank 8*tig+gid).
// ---------------------------------------------------------------------------
#define QS_STRIDE 68
#define KS_STRIDE 68
#define VS_STRIDE 72
#define QS_FLOATS (128 * QS_STRIDE)   // 8704
#define KS_FLOATS (192 * KS_STRIDE)   // 13056
#define VS_FLOATS (192 * VS_STRIDE)   // 13824
#define ATTN_SMEM_BYTES ((QS_FLOATS + KS_FLOATS + VS_FLOATS) * 4)   // 142336

__global__ __launch_bounds__(256, 1)
void attn_tc(const float* __restrict__ Q, const float* __restrict__ K,
             const float* __restrict__ V, float* __restrict__ O)
{
    extern __shared__ float sm[];
    const uint32_t smQ = smem_u32(sm);
    const uint32_t smK = smQ + QS_FLOATS * 4u;
    const uint32_t smV = smK + KS_FLOATS * 4u;

    const int win  = blockIdx.x;
    const int h    = blockIdx.y;
    const int b    = blockIdx.z;
    const int tid  = threadIdx.x;
    const int wid  = tid >> 5;
    const int lane = tid & 31;
    const int gid  = lane >> 2;   // 0..7
    const int tg   = lane & 3;    // 0..3

    // ---- stage Q (128 x 64), K (192 x 64), V (192 x 64) ----
    const float* Qg = Q + ((size_t)(b * SEQ + win * WIN)) * DMODEL + h * HDIM;
    for (int i = tid; i < 128 * 16; i += 256) {
        const int row = i >> 4, c4 = i & 15;
        cp_async16(smQ + (uint32_t)(row * QS_STRIDE + c4 * 4) * 4u,
                   Qg + (size_t)row * DMODEL + c4 * 4);
    }
    for (int i = tid; i < 192 * 16; i += 256) {
        const int row = i >> 4, c4 = i & 15;
        const int tok = (row < 64) ? row : (win * WIN + row - 64);
        const size_t src = ((size_t)(b * SEQ + tok)) * DMODEL + h * HDIM + c4 * 4;
        cp_async16(smK + (uint32_t)(row * KS_STRIDE + c4 * 4) * 4u, K + src);
        cp_async16(smV + (uint32_t)(row * VS_STRIDE + c4 * 4) * 4u, V + src);
    }
    CP_COMMIT(); CP_WAIT0();
    __syncthreads();

    // ---- Q A-frags: 8 k-steps x 4 regs ----
    uint32_t aQ[8][4];
    {
        const uint32_t qb = smQ +
            (uint32_t)((wid * 16 + (lane & 15)) * QS_STRIDE + ((lane & 16) ? 4 : 0)) * 4u;
#pragma unroll
        for (int ks = 0; ks < 8; ks++) ldsm_x4(aQ[ks], qb + ks * 32u);
    }

    // ---- S = Q K^T : 24 n-frags (cols 8*nf .. 8*nf+7) ----
    float sf[24][4];
#pragma unroll
    for (int nf = 0; nf < 24; nf++)
#pragma unroll
        for (int r = 0; r < 4; r++) sf[nf][r] = 0.f;

#pragma unroll
    for (int ks = 0; ks < 8; ks++) {
        uint32_t bf[12][4];
#pragma unroll
        for (int p = 0; p < 12; p++) {
            const int nrow = (2 * p + ((lane >> 4) & 1)) * 8 + (lane & 7);
            const uint32_t addr = smK +
                (uint32_t)(nrow * KS_STRIDE + ((lane & 8) ? 4 : 0)) * 4u + ks * 32u;
            ldsm_x4(bf[p], addr);
        }
#pragma unroll
        for (int p = 0; p < 12; p++) {
            mma16x8x8(sf[2 * p],     aQ[ks], &bf[p][0]);
            mma16x8x8(sf[2 * p + 1], aQ[ks], &bf[p][2]);
        }
    }

    // ---- softmax (exact; rows rA=gid, rB=gid+8; scale 1/8 folded into exp) ----
    float mA = -1e30f, mB = -1e30f;
#pragma unroll
    for (int nf = 0; nf < 24; nf++) {
        mA = fmaxf(mA, fmaxf(sf[nf][0], sf[nf][1]));
        mB = fmaxf(mB, fmaxf(sf[nf][2], sf[nf][3]));
    }
    mA = fmaxf(mA, __shfl_xor_sync(0xffffffffu, mA, 1));
    mA = fmaxf(mA, __shfl_xor_sync(0xffffffffu, mA, 2));
    mB = fmaxf(mB, __shfl_xor_sync(0xffffffffu, mB, 1));
    mB = fmaxf(mB, __shfl_xor_sync(0xffffffffu, mB, 2));

    float lA = 0.f, lB = 0.f;
#pragma unroll
    for (int nf = 0; nf < 24; nf++) {
        float p0 = __expf((sf[nf][0] - mA) * 0.125f);
        float p1 = __expf((sf[nf][1] - mA) * 0.125f);
        float p2 = __expf((sf[nf][2] - mB) * 0.125f);
        float p3 = __expf((sf[nf][3] - mB) * 0.125f);
        sf[nf][0] = p0; sf[nf][1] = p1; sf[nf][2] = p2; sf[nf][3] = p3;
        lA += p0 + p1; lB += p2 + p3;
    }
    lA += __shfl_xor_sync(0xffffffffu, lA, 1);
    lA += __shfl_xor_sync(0xffffffffu, lA, 2);
    lB += __shfl_xor_sync(0xffffffffu, lB, 1);
    lB += __shfl_xor_sync(0xffffffffu, lB, 2);

    // ---- O = P V : P frag kk (C-layout) -> A-frag via quad shuffles ----
    float oc[8][4];
#pragma unroll
    for (int nf = 0; nf < 8; nf++)
#pragma unroll
        for (int r = 0; r < 4; r++) oc[nf][r] = 0.f;

    const int src_lo = (lane & 28) | (tg >> 1);
    const int src_hi = src_lo + 2;
    const bool odd   = tg & 1;

#pragma unroll
    for (int kk = 0; kk < 24; kk++) {
        float t0, t1;
        t0 = __shfl_sync(0xffffffffu, sf[kk][0], src_lo);
        t1 = __shfl_sync(0xffffffffu, sf[kk][1], src_lo);
        const float a0f = odd ? t1 : t0;
        t0 = __shfl_sync(0xffffffffu, sf[kk][2], src_lo);
        t1 = __shfl_sync(0xffffffffu, sf[kk][3], src_lo);
        const float a1f = odd ? t1 : t0;
        t0 = __shfl_sync(0xffffffffu, sf[kk][0], src_hi);
        t1 = __shfl_sync(0xffffffffu, sf[kk][1], src_hi);
        const float a2f = odd ? t1 : t0;
        t0 = __shfl_sync(0xffffffffu, sf[kk][2], src_hi);
        t1 = __shfl_sync(0xffffffffu, sf[kk][3], src_hi);
        const float a3f = odd ? t1 : t0;

        uint32_t a[4];
        a[0] = __float_as_uint(to_tf32(a0f));
        a[1] = __float_as_uint(to_tf32(a1f));
        a[2] = __float_as_uint(to_tf32(a2f));
        a[3] = __float_as_uint(to_tf32(a3f));

        // V b-frags: b0 = V[key = 8kk+tg][dim = 8nf+gid], b1 = +4 keys
        const float* vrow0 = sm + QS_FLOATS + KS_FLOATS + (8 * kk + tg) * VS_STRIDE + gid;
        const float* vrow1 = vrow0 + 4 * VS_STRIDE;
#pragma unroll
        for (int nf = 0; nf < 8; nf++) {
            uint32_t bb[2];
            bb[0] = __float_as_uint(vrow0[nf * 8]);
            bb[1] = __float_as_uint(vrow1[nf * 8]);
            mma16x8x8(oc[nf], a, bb);
        }
    }

    // ---- epilogue: divide by l, round to tf32 (feeds Wo GEMM), store ----
    const float invA = 1.f / lA, invB = 1.f / lB;
    const int qrow = win * WIN + wid * 16 + gid;
    float* outA = O + ((size_t)(b * SEQ + qrow)) * DMODEL + h * HDIM;
    float* outB = outA + 8 * DMODEL;
#pragma unroll
    for (int nf = 0; nf < 8; nf++) {
        const int col = nf * 8 + 2 * tg;
        *(float2*)(outA + col) = make_float2(to_tf32(oc[nf][0] * invA),
                                             to_tf32(oc[nf][1] * invA));
        *(float2*)(outB + col) = make_float2(to_tf32(oc[nf][2] * invB),
                                             to_tf32(oc[nf][3] * invB));
    }
}

// ---------------------------------------------------------------------------
extern "C" void kernel_launch(void* const* d_in, const int* in_sizes, int n_in,
                              void* d_out, int out_size)
{
    const float* x  = (const float*)d_in[0];
    const float* Wq = (const float*)d_in[1];
    const float* Wk = (const float*)d_in[2];
    const float* Wv = (const float*)d_in[3];
    const float* Wo = (const float*)d_in[4];
    float* out = (float*)d_out;

    float *q, *k, *v, *att, *xr, *wq, *wk, *wv, *wo;
    cudaGetSymbolAddress((void**)&q,   g_q);
    cudaGetSymbolAddress((void**)&k,   g_k);
    cudaGetSymbolAddress((void**)&v,   g_v);
    cudaGetSymbolAddress((void**)&att, g_att);
    cudaGetSymbolAddress((void**)&xr,  g_xr);
    cudaGetSymbolAddress((void**)&wq,  g_wq);
    cudaGetSymbolAddress((void**)&wk,  g_wk);
    cudaGetSymbolAddress((void**)&wv,  g_wv);
    cudaGetSymbolAddress((void**)&wo,  g_wo);

    cudaFuncSetAttribute(gemm_tf32, cudaFuncAttributeMaxDynamicSharedMemorySize,
                         GEMM_SMEM_BYTES);
    cudaFuncSetAttribute(attn_tc, cudaFuncAttributeMaxDynamicSharedMemorySize,
                         ATTN_SMEM_BYTES);

    // tf32-round GEMM inputs
    round_tf32_kernel<<<2048, 256>>>(x,  xr, MROWS * DMODEL / 4);
    round_tf32_kernel<<<512,  256>>>(Wq, wq, DMODEL * DMODEL / 4);
    round_tf32_kernel<<<512,  256>>>(Wk, wk, DMODEL * DMODEL / 4);
    round_tf32_kernel<<<512,  256>>>(Wv, wv, DMODEL * DMODEL / 4);
    round_tf32_kernel<<<512,  256>>>(Wo, wo, DMODEL * DMODEL / 4);

    // fused QKV projection (outputs tf32-rounded: they feed attention mma)
    dim3 gqkv(DMODEL / BN, MROWS / BM, 3);   // (8, 128, 3)
    gemm_tf32<<<gqkv, 256, GEMM_SMEM_BYTES>>>(xr, wq, wk, wv, q, k, v, 1);

    dim3 ga(NWIN, NHEADS, BATCH);            // (64, 16, 2)
    attn_tc<<<ga, 256, ATTN_SMEM_BYTES>>>(q, k, v, att);

    dim3 go(DMODEL / BN, MROWS / BM, 1);     // (8, 128, 1)
    gemm_tf32<<<go, 256, GEMM_SMEM_BYTES>>>(att, wo, wo, wo, out, out, out, 0);
}

// round 9
// speedup vs baseline: 4.9850x; 1.2357x over previous
#include <cuda_runtime.h>
#include <cuda_fp16.h>
#include <cstdint>

// ---------------------------------------------------------------------------
// Problem constants
// ---------------------------------------------------------------------------
#define BATCH 2
#define SEQ   8192
#define DMODEL 1024
#define NHEADS 16
#define HDIM  64
#define WIN   128
#define MROWS (BATCH*SEQ)          // 16384
#define NWIN  (SEQ/WIN)            // 64

// ---------------------------------------------------------------------------
// Scratch (allocation-free rule: __device__ globals) — fp16 pipeline
// ---------------------------------------------------------------------------
__device__ __half g_xh [(size_t)MROWS * DMODEL];
__device__ __half g_qh [(size_t)MROWS * DMODEL];
__device__ __half g_kh [(size_t)MROWS * DMODEL];
__device__ __half g_vh [(size_t)MROWS * DMODEL];
__device__ __half g_ah [(size_t)MROWS * DMODEL];
__device__ __half g_wqh[(size_t)DMODEL * DMODEL];
__device__ __half g_wkh[(size_t)DMODEL * DMODEL];
__device__ __half g_wvh[(size_t)DMODEL * DMODEL];
__device__ __half g_woh[(size_t)DMODEL * DMODEL];

// ---------------------------------------------------------------------------
// Helpers
// ---------------------------------------------------------------------------
__device__ __forceinline__ uint32_t smem_u32(const void* p) {
    uint32_t a;
    asm("{ .reg .u64 t; cvta.to.shared.u64 t, %1; cvt.u32.u64 %0, t; }" : "=r"(a) : "l"(p));
    return a;
}
__device__ __forceinline__ void cp_async16(uint32_t dst, const void* src) {
    asm volatile("cp.async.cg.shared.global [%0], [%1], 16;" :: "r"(dst), "l"(src));
}
#define CP_COMMIT() asm volatile("cp.async.commit_group;" ::: "memory")
#define CP_WAIT1()  asm volatile("cp.async.wait_group 1;" ::: "memory")
#define CP_WAIT0()  asm volatile("cp.async.wait_group 0;" ::: "memory")

// fp16 m16n8k16 mma, fp32 accum (sm_80-era PTX — compiles for plain sm_103)
__device__ __forceinline__ void mma16x8x16(float* c, const uint32_t* a, const uint32_t* b) {
    asm volatile(
        "mma.sync.aligned.m16n8k16.row.col.f32.f16.f16.f32 "
        "{%0,%1,%2,%3}, {%4,%5,%6,%7}, {%8,%9}, {%0,%1,%2,%3};"
        : "+f"(c[0]), "+f"(c[1]), "+f"(c[2]), "+f"(c[3])
        : "r"(a[0]), "r"(a[1]), "r"(a[2]), "r"(a[3]), "r"(b[0]), "r"(b[1]));
}
__device__ __forceinline__ void ldsm_x4(uint32_t* r, uint32_t addr) {
    asm volatile("ldmatrix.sync.aligned.m8n8.x4.shared.b16 {%0,%1,%2,%3}, [%4];"
                 : "=r"(r[0]), "=r"(r[1]), "=r"(r[2]), "=r"(r[3]) : "r"(addr));
}
__device__ __forceinline__ void ldsm_x4t(uint32_t* r, uint32_t addr) {
    asm volatile("ldmatrix.sync.aligned.m8n8.x4.trans.shared.b16 {%0,%1,%2,%3}, [%4];"
                 : "=r"(r[0]), "=r"(r[1]), "=r"(r[2]), "=r"(r[3]) : "r"(addr));
}
__device__ __forceinline__ uint32_t pack_h2(float lo, float hi) {
    __half2 h = __floats2half2_rn(lo, hi);
    return *(uint32_t*)&h;
}

// ---------------------------------------------------------------------------
// fp16 mma GEMM:  C[m,n] = sum_k A[m,k]*B[n,k]    (both half, K-major)
// CTA 128x128, BK=64 halfs, 256 threads (8 warps, warp tile 64x32), 2-stage.
// Smem rows: 64 halfs + 8 pad = 72 halfs = 144B (ldmatrix conflict-free:
// row r starts at bank 4r mod 32, each matrix row spans 4 banks).
// blockIdx.z selects (B, C) pair; half output when Ch* set (QKV), else float.
// ---------------------------------------------------------------------------
#define BM 128
#define BN 128
#define BKH 64
#define KSH 72                            // halfs per smem row
#define TILE_HALFS (128 * KSH)            // 9216
#define STAGE_BYTES (2 * TILE_HALFS * 2)  // A+B one stage = 36864
#define GEMM_SMEM_BYTES (2 * STAGE_BYTES) // 73728
#define NCH (DMODEL / BKH)                // 16

__global__ __launch_bounds__(256, 2)
void gemm_f16(const __half* __restrict__ A,
              const __half* __restrict__ B0, const __half* __restrict__ B1,
              const __half* __restrict__ B2,
              float* __restrict__ Cf,
              __half* __restrict__ Ch0, __half* __restrict__ Ch1,
              __half* __restrict__ Ch2)
{
    const __half* B  = (blockIdx.z == 0) ? B0 : (blockIdx.z == 1) ? B1 : B2;
    __half*       Ch = (blockIdx.z == 0) ? Ch0 : (blockIdx.z == 1) ? Ch1 : Ch2;

    extern __shared__ __half smh[];
    const uint32_t smBase = smem_u32(smh);

    const int tid  = threadIdx.x;
    const int wid  = tid >> 5;
    const int lane = tid & 31;
    const int gid  = lane >> 2;
    const int tig  = lane & 3;
    const int moff = (wid & 1) * 64;
    const int noff = (wid >> 1) * 32;
    const int bm   = blockIdx.y * BM;
    const int bn   = blockIdx.x * BN;

    // ldmatrix per-lane base addresses (stage 0, kstep 0)
    uint32_t aAddr[4], bAddr[2];
#pragma unroll
    for (int mi = 0; mi < 4; mi++) {
        const int arow = moff + mi * 16 + (lane & 15);
        aAddr[mi] = smBase + (uint32_t)(arow * KSH) * 2u + ((lane & 16) ? 16u : 0u);
    }
#pragma unroll
    for (int p = 0; p < 2; p++) {
        const int nrow = noff + p * 16 + ((lane >> 4) & 1) * 8 + (lane & 7);
        bAddr[p] = smBase + (uint32_t)(TILE_HALFS + nrow * KSH) * 2u + ((lane & 8) ? 16u : 0u);
    }

    float acc[4][4][4];
#pragma unroll
    for (int i = 0; i < 4; i++)
#pragma unroll
        for (int j = 0; j < 4; j++)
#pragma unroll
            for (int r = 0; r < 4; r++) acc[i][j][r] = 0.f;

    auto load_chunk = [&](int ch, int s) {
        const int k0 = ch * BKH;
        const uint32_t aBase = smBase + (uint32_t)s * STAGE_BYTES;
        const uint32_t bBase = aBase + TILE_HALFS * 2u;
#pragma unroll
        for (int i = 0; i < 4; i++) {
            const int c   = tid + i * 256;
            const int row = c >> 3;
            const int col = c & 7;                       // 16B (8-half) chunk
            cp_async16(aBase + row * (KSH * 2) + col * 16,
                       A + (size_t)(bm + row) * DMODEL + k0 + col * 8);
            cp_async16(bBase + row * (KSH * 2) + col * 16,
                       B + (size_t)(bn + row) * DMODEL + k0 + col * 8);
        }
        CP_COMMIT();
    };

    load_chunk(0, 0);

    for (int ch = 0; ch < NCH; ch++) {
        const int s = ch & 1;
        if (ch + 1 < NCH) { load_chunk(ch + 1, s ^ 1); CP_WAIT1(); }
        else              { CP_WAIT0(); }
        __syncthreads();

        const uint32_t soff = (uint32_t)s * STAGE_BYTES;
#pragma unroll
        for (int ks = 0; ks < 4; ks++) {                 // k16 per step = 32B
            const uint32_t kOff = soff + ks * 32u;
            uint32_t af[4][4], bf[2][4];
#pragma unroll
            for (int mi = 0; mi < 4; mi++) ldsm_x4(af[mi], aAddr[mi] + kOff);
#pragma unroll
            for (int p = 0; p < 2; p++)    ldsm_x4(bf[p],  bAddr[p] + kOff);
#pragma unroll
            for (int mi = 0; mi < 4; mi++)
#pragma unroll
                for (int ni = 0; ni < 4; ni++)
                    mma16x8x16(acc[mi][ni], af[mi], &bf[ni >> 1][(ni & 1) * 2]);
        }
        __syncthreads();
    }

    // epilogue
    if (Ch) {
#pragma unroll
        for (int mi = 0; mi < 4; mi++)
#pragma unroll
            for (int ni = 0; ni < 4; ni++) {
                const int row0 = bm + moff + mi * 16 + gid;
                const int col0 = bn + noff + ni * 8 + 2 * tig;
                __half2* p0 = (__half2*)&Ch[(size_t)row0 * DMODEL + col0];
                __half2* p1 = (__half2*)&Ch[(size_t)(row0 + 8) * DMODEL + col0];
                *p0 = __floats2half2_rn(acc[mi][ni][0], acc[mi][ni][1]);
                *p1 = __floats2half2_rn(acc[mi][ni][2], acc[mi][ni][3]);
            }
    } else {
#pragma unroll
        for (int mi = 0; mi < 4; mi++)
#pragma unroll
            for (int ni = 0; ni < 4; ni++) {
                const int row0 = bm + moff + mi * 16 + gid;
                const int col0 = bn + noff + ni * 8 + 2 * tig;
                *(float2*)&Cf[(size_t)row0 * DMODEL + col0] =
                    make_float2(acc[mi][ni][0], acc[mi][ni][1]);
                *(float2*)&Cf[(size_t)(row0 + 8) * DMODEL + col0] =
                    make_float2(acc[mi][ni][2], acc[mi][ni][3]);
            }
    }
}

// ---------------------------------------------------------------------------
// f32 -> f16 conversion prep
// ---------------------------------------------------------------------------
__global__ void f32_to_f16_kernel(const float* __restrict__ in, __half* __restrict__ out, int n8)
{
    for (int i = blockIdx.x * blockDim.x + threadIdx.x; i < n8; i += gridDim.x * blockDim.x) {
        float4 v0 = ((const float4*)in)[2 * i];
        float4 v1 = ((const float4*)in)[2 * i + 1];
        uint4 o;
        o.x = pack_h2(v0.x, v0.y); o.y = pack_h2(v0.z, v0.w);
        o.z = pack_h2(v1.x, v1.y); o.w = pack_h2(v1.z, v1.w);
        ((uint4*)out)[i] = o;
    }
}

__global__ void conv_weights_kernel(const float* __restrict__ w0, const float* __restrict__ w1,
                                    const float* __restrict__ w2, const float* __restrict__ w3,
                                    __half* __restrict__ o0, __half* __restrict__ o1,
                                    __half* __restrict__ o2, __half* __restrict__ o3, int n8)
{
    const float* in  = (blockIdx.y == 0) ? w0 : (blockIdx.y == 1) ? w1 :
                       (blockIdx.y == 2) ? w2 : w3;
    __half* out = (blockIdx.y == 0) ? o0 : (blockIdx.y == 1) ? o1 :
                  (blockIdx.y == 2) ? o2 : o3;
    for (int i = blockIdx.x * blockDim.x + threadIdx.x; i < n8; i += gridDim.x * blockDim.x) {
        float4 v0 = ((const float4*)in)[2 * i];
        float4 v1 = ((const float4*)in)[2 * i + 1];
        uint4 o;
        o.x = pack_h2(v0.x, v0.y); o.y = pack_h2(v0.z, v0.w);
        o.z = pack_h2(v1.x, v1.y); o.w = pack_h2(v1.z, v1.w);
        ((uint4*)out)[i] = o;
    }
}

// ---------------------------------------------------------------------------
// fp16 tensor-core hybrid attention.
// One CTA per (window, head, batch); 8 warps, warp owns 16 query rows.
// 192 keys (64 global + 128 local) in smem. S = Q K^T (m16n8k16), exact
// softmax in registers, P packs directly into fp16 A-frags (C-layout k-pairs
// == A-frag k-pairs: no shuffles), O = P V with V B-frags via ldmatrix.trans.
// Smem rows: 64 halfs + 8 pad = 72 halfs.
// ---------------------------------------------------------------------------
#define QS_HALFS (128 * KSH)    // 9216
#define KS_HALFS (192 * KSH)    // 13824
#define VS_HALFS (192 * KSH)
#define ATTN_SMEM_BYTES ((QS_HALFS + KS_HALFS + VS_HALFS) * 2)   // 73728

__global__ __launch_bounds__(256, 1)
void attn_f16(const __half* __restrict__ Q, const __half* __restrict__ K,
              const __half* __restrict__ V, __half* __restrict__ O)
{
    extern __shared__ __half smh[];
    const uint32_t smQ = smem_u32(smh);
    const uint32_t smK = smQ + QS_HALFS * 2u;
    const uint32_t smV = smK + KS_HALFS * 2u;

    const int win  = blockIdx.x;
    const int h    = blockIdx.y;
    const int b    = blockIdx.z;
    const int tid  = threadIdx.x;
    const int wid  = tid >> 5;
    const int lane = tid & 31;
    const int gid  = lane >> 2;   // 0..7
    const int tg   = lane & 3;    // 0..3

    // ---- stage Q (128x64), K (192x64), V (192x64) halfs ----
    const __half* Qg = Q + ((size_t)(b * SEQ + win * WIN)) * DMODEL + h * HDIM;
    for (int i = tid; i < 128 * 8; i += 256) {
        const int row = i >> 3, c8 = i & 7;
        cp_async16(smQ + (uint32_t)(row * KSH) * 2u + c8 * 16,
                   Qg + (size_t)row * DMODEL + c8 * 8);
    }
    for (int i = tid; i < 192 * 8; i += 256) {
        const int row = i >> 3, c8 = i & 7;
        const int tok = (row < 64) ? row : (win * WIN + row - 64);
        const size_t src = ((size_t)(b * SEQ + tok)) * DMODEL + h * HDIM + c8 * 8;
        cp_async16(smK + (uint32_t)(row * KSH) * 2u + c8 * 16, K + src);
        cp_async16(smV + (uint32_t)(row * KSH) * 2u + c8 * 16, V + src);
    }
    CP_COMMIT(); CP_WAIT0();
    __syncthreads();

    // ---- Q A-frags: 4 k16-steps ----
    uint32_t aQ[4][4];
    {
        const uint32_t qb = smQ + (uint32_t)((wid * 16 + (lane & 15)) * KSH) * 2u +
                            ((lane & 16) ? 16u : 0u);
#pragma unroll
        for (int ks = 0; ks < 4; ks++) ldsm_x4(aQ[ks], qb + ks * 32u);
    }

    // ---- S = Q K^T : 24 n8-frags over 192 keys ----
    float sf[24][4];
#pragma unroll
    for (int nf = 0; nf < 24; nf++)
#pragma unroll
        for (int r = 0; r < 4; r++) sf[nf][r] = 0.f;

#pragma unroll
    for (int ks = 0; ks < 4; ks++) {
        uint32_t bf[12][4];
#pragma unroll
        for (int p = 0; p < 12; p++) {
            const int nrow = p * 16 + ((lane >> 4) & 1) * 8 + (lane & 7);
            ldsm_x4(bf[p], smK + (uint32_t)(nrow * KSH) * 2u +
                           ((lane & 8) ? 16u : 0u) + ks * 32u);
        }
#pragma unroll
        for (int p = 0; p < 12; p++) {
            mma16x8x16(sf[2 * p],     aQ[ks], &bf[p][0]);
            mma16x8x16(sf[2 * p + 1], aQ[ks], &bf[p][2]);
        }
    }

    // ---- exact softmax (rows rA = gid, rB = gid+8; scale 1/8 in exp arg) ----
    float mA = -1e30f, mB = -1e30f;
#pragma unroll
    for (int nf = 0; nf < 24; nf++) {
        mA = fmaxf(mA, fmaxf(sf[nf][0], sf[nf][1]));
        mB = fmaxf(mB, fmaxf(sf[nf][2], sf[nf][3]));
    }
    mA = fmaxf(mA, __shfl_xor_sync(0xffffffffu, mA, 1));
    mA = fmaxf(mA, __shfl_xor_sync(0xffffffffu, mA, 2));
    mB = fmaxf(mB, __shfl_xor_sync(0xffffffffu, mB, 1));
    mB = fmaxf(mB, __shfl_xor_sync(0xffffffffu, mB, 2));

    float lA = 0.f, lB = 0.f;
#pragma unroll
    for (int nf = 0; nf < 24; nf++) {
        float p0 = __expf((sf[nf][0] - mA) * 0.125f);
        float p1 = __expf((sf[nf][1] - mA) * 0.125f);
        float p2 = __expf((sf[nf][2] - mB) * 0.125f);
        float p3 = __expf((sf[nf][3] - mB) * 0.125f);
        sf[nf][0] = p0; sf[nf][1] = p1; sf[nf][2] = p2; sf[nf][3] = p3;
        lA += p0 + p1; lB += p2 + p3;
    }
    lA += __shfl_xor_sync(0xffffffffu, lA, 1);
    lA += __shfl_xor_sync(0xffffffffu, lA, 2);
    lB += __shfl_xor_sync(0xffffffffu, lB, 1);
    lB += __shfl_xor_sync(0xffffffffu, lB, 2);

    // ---- O = P V : 12 k16-steps, 8 n8-frags (64 dims) ----
    float oc[8][4];
#pragma unroll
    for (int nf = 0; nf < 8; nf++)
#pragma unroll
        for (int r = 0; r < 4; r++) oc[nf][r] = 0.f;

#pragma unroll
    for (int j = 0; j < 12; j++) {
        // P A-frag for keys 16j..16j+15: identity relayout from C-frags
        uint32_t a[4];
        a[0] = pack_h2(sf[2 * j][0],     sf[2 * j][1]);
        a[1] = pack_h2(sf[2 * j][2],     sf[2 * j][3]);
        a[2] = pack_h2(sf[2 * j + 1][0], sf[2 * j + 1][1]);
        a[3] = pack_h2(sf[2 * j + 1][2], sf[2 * j + 1][3]);

        // V B-frags via ldmatrix.trans: rows = keys, cols = dims
        const uint32_t vb = smV + (uint32_t)((j * 16 + ((lane >> 3) & 1) * 8 + (lane & 7)) * KSH) * 2u +
                            ((lane & 16) ? 16u : 0u);
#pragma unroll
        for (int t = 0; t < 2; t++) {        // dim groups 32t .. 32t+31
            uint32_t bv[4];
            ldsm_x4t(bv, vb + t * 64u);      // n16 = 32 halfs? no: 16 dims = 32B
            mma16x8x16(oc[4 * t],     a, &bv[0]);
            mma16x8x16(oc[4 * t + 1], a, &bv[2]);
            uint32_t bv2[4];
            ldsm_x4t(bv2, vb + t * 64u + 32u);
            mma16x8x16(oc[4 * t + 2], a, &bv2[0]);
            mma16x8x16(oc[4 * t + 3], a, &bv2[2]);
        }
    }

    // ---- epilogue: divide by l, write half ----
    const float invA = 1.f / lA, invB = 1.f / lB;
    const int qrow = win * WIN + wid * 16 + gid;
    __half* outA = O + ((size_t)(b * SEQ + qrow)) * DMODEL + h * HDIM;
    __half* outB = outA + 8 * DMODEL;
#pragma unroll
    for (int nf = 0; nf < 8; nf++) {
        const int col = nf * 8 + 2 * tg;
        *(__half2*)(outA + col) = __floats2half2_rn(oc[nf][0] * invA, oc[nf][1] * invA);
        *(__half2*)(outB + col) = __floats2half2_rn(oc[nf][2] * invB, oc[nf][3] * invB);
    }
}

// ---------------------------------------------------------------------------
extern "C" void kernel_launch(void* const* d_in, const int* in_sizes, int n_in,
                              void* d_out, int out_size)
{
    const float* x  = (const float*)d_in[0];
    const float* Wq = (const float*)d_in[1];
    const float* Wk = (const float*)d_in[2];
    const float* Wv = (const float*)d_in[3];
    const float* Wo = (const float*)d_in[4];
    float* out = (float*)d_out;

    __half *xh, *qh, *kh, *vh, *ah, *wqh, *wkh, *wvh, *woh;
    cudaGetSymbolAddress((void**)&xh,  g_xh);
    cudaGetSymbolAddress((void**)&qh,  g_qh);
    cudaGetSymbolAddress((void**)&kh,  g_kh);
    cudaGetSymbolAddress((void**)&vh,  g_vh);
    cudaGetSymbolAddress((void**)&ah,  g_ah);
    cudaGetSymbolAddress((void**)&wqh, g_wqh);
    cudaGetSymbolAddress((void**)&wkh, g_wkh);
    cudaGetSymbolAddress((void**)&wvh, g_wvh);
    cudaGetSymbolAddress((void**)&woh, g_woh);

    cudaFuncSetAttribute(gemm_f16, cudaFuncAttributeMaxDynamicSharedMemorySize,
                         GEMM_SMEM_BYTES);
    cudaFuncSetAttribute(attn_f16, cudaFuncAttributeMaxDynamicSharedMemorySize,
                         ATTN_SMEM_BYTES);

    // f32 -> f16 prep
    f32_to_f16_kernel<<<1024, 256>>>(x, xh, MROWS * DMODEL / 8);
    dim3 gw(256, 4);
    conv_weights_kernel<<<gw, 256>>>(Wq, Wk, Wv, Wo, wqh, wkh, wvh, woh,
                                     DMODEL * DMODEL / 8);

    // fused QKV projection (half outputs feed attention)
    dim3 gqkv(DMODEL / BN, MROWS / BM, 3);   // (8, 128, 3)
    gemm_f16<<<gqkv, 256, GEMM_SMEM_BYTES>>>(xh, wqh, wkh, wvh,
                                             nullptr, qh, kh, vh);

    dim3 ga(NWIN, NHEADS, BATCH);            // (64, 16, 2)
    attn_f16<<<ga, 256, ATTN_SMEM_BYTES>>>(qh, kh, vh, ah);

    // output projection (float output)
    dim3 go(DMODEL / BN, MROWS / BM, 1);
    gemm_f16<<<go, 256, GEMM_SMEM_BYTES>>>(ah, woh, woh, woh,
                                           out, nullptr, nullptr, nullptr);
}

// round 12
// speedup vs baseline: 7.3998x; 1.4844x over previous
#include <cuda_runtime.h>
#include <cuda_fp16.h>
#include <cstdint>

// ---------------------------------------------------------------------------
// Problem constants
// ---------------------------------------------------------------------------
#define BATCH 2
#define SEQ   8192
#define DMODEL 1024
#define NHEADS 16
#define HDIM  64
#define WIN   128
#define MROWS (BATCH*SEQ)          // 16384
#define NWIN  (SEQ/WIN)            // 64

// ---------------------------------------------------------------------------
// Scratch (allocation-free rule: __device__ globals) — fp16 pipeline
// ---------------------------------------------------------------------------
__device__ __half g_xh [(size_t)MROWS * DMODEL];
__device__ __half g_qh [(size_t)MROWS * DMODEL];
__device__ __half g_kh [(size_t)MROWS * DMODEL];
__device__ __half g_vh [(size_t)MROWS * DMODEL];
__device__ __half g_ah [(size_t)MROWS * DMODEL];
__device__ __half g_wqh[(size_t)DMODEL * DMODEL];
__device__ __half g_wkh[(size_t)DMODEL * DMODEL];
__device__ __half g_wvh[(size_t)DMODEL * DMODEL];
__device__ __half g_woh[(size_t)DMODEL * DMODEL];

// ---------------------------------------------------------------------------
// Helpers
// ---------------------------------------------------------------------------
__device__ __forceinline__ uint32_t smem_u32(const void* p) {
    uint32_t a;
    asm("{ .reg .u64 t; cvta.to.shared.u64 t, %1; cvt.u32.u64 %0, t; }" : "=r"(a) : "l"(p));
    return a;
}
__device__ __forceinline__ void cp_async16(uint32_t dst, const void* src) {
    asm volatile("cp.async.cg.shared.global [%0], [%1], 16;" :: "r"(dst), "l"(src));
}
#define CP_COMMIT() asm volatile("cp.async.commit_group;" ::: "memory")
#define CP_WAIT1()  asm volatile("cp.async.wait_group 1;" ::: "memory")
#define CP_WAIT0()  asm volatile("cp.async.wait_group 0;" ::: "memory")

// fp16 m16n8k16 mma, fp32 accum (sm_80-era PTX — compiles for plain sm_103)
__device__ __forceinline__ void mma16x8x16(float* c, const uint32_t* a, const uint32_t* b) {
    asm volatile(
        "mma.sync.aligned.m16n8k16.row.col.f32.f16.f16.f32 "
        "{%0,%1,%2,%3}, {%4,%5,%6,%7}, {%8,%9}, {%0,%1,%2,%3};"
        : "+f"(c[0]), "+f"(c[1]), "+f"(c[2]), "+f"(c[3])
        : "r"(a[0]), "r"(a[1]), "r"(a[2]), "r"(a[3]), "r"(b[0]), "r"(b[1]));
}
__device__ __forceinline__ void ldsm_x4(uint32_t* r, uint32_t addr) {
    asm volatile("ldmatrix.sync.aligned.m8n8.x4.shared.b16 {%0,%1,%2,%3}, [%4];"
                 : "=r"(r[0]), "=r"(r[1]), "=r"(r[2]), "=r"(r[3]) : "r"(addr));
}
__device__ __forceinline__ void ldsm_x4t(uint32_t* r, uint32_t addr) {
    asm volatile("ldmatrix.sync.aligned.m8n8.x4.trans.shared.b16 {%0,%1,%2,%3}, [%4];"
                 : "=r"(r[0]), "=r"(r[1]), "=r"(r[2]), "=r"(r[3]) : "r"(addr));
}
__device__ __forceinline__ uint32_t pack_h2(float lo, float hi) {
    __half2 h = __floats2half2_rn(lo, hi);
    return *(uint32_t*)&h;
}

// ---------------------------------------------------------------------------
// fp16 mma GEMM:  C[m,n] = sum_k A[m,k]*B[n,k]    (both half, K-major)
// CTA 128x128, BK=64 halfs, 256 threads (8 warps, warp tile 64x32).
// 3-stage cp.async pipeline; ordering per chunk: wait -> barrier -> issue
// next-next load -> compute. The barrier precedes the load issue, so writes
// into a stage can never race reads of that stage from the prior iteration.
// Smem rows: 64 halfs + 8 pad = 72 halfs = 144B (ldmatrix conflict-free).
// blockIdx.z selects (B, C) pair; half output when Ch* set (QKV), else float.
// ---------------------------------------------------------------------------
#define BM 128
#define BN 128
#define BKH 64
#define KSH 72                            // halfs per smem row
#define TILE_HALFS (128 * KSH)            // 9216
#define STAGE_BYTES (2 * TILE_HALFS * 2)  // A+B one stage = 36864
#define NSTAGE 3
#define GEMM_SMEM_BYTES (NSTAGE * STAGE_BYTES) // 110592
#define NCH (DMODEL / BKH)                // 16

__global__ __launch_bounds__(256, 2)
void gemm_f16(const __half* __restrict__ A,
              const __half* __restrict__ B0, const __half* __restrict__ B1,
              const __half* __restrict__ B2,
              float* __restrict__ Cf,
              __half* __restrict__ Ch0, __half* __restrict__ Ch1,
              __half* __restrict__ Ch2)
{
    const __half* B  = (blockIdx.z == 0) ? B0 : (blockIdx.z == 1) ? B1 : B2;
    __half*       Ch = (blockIdx.z == 0) ? Ch0 : (blockIdx.z == 1) ? Ch1 : Ch2;

    extern __shared__ __half smh[];
    const uint32_t smBase = smem_u32(smh);

    const int tid  = threadIdx.x;
    const int wid  = tid >> 5;
    const int lane = tid & 31;
    const int gid  = lane >> 2;
    const int tig  = lane & 3;
    const int moff = (wid & 1) * 64;
    const int noff = (wid >> 1) * 32;
    const int bm   = blockIdx.y * BM;
    const int bn   = blockIdx.x * BN;

    // ldmatrix per-lane base addresses (stage 0, kstep 0)
    uint32_t aAddr[4], bAddr[2];
#pragma unroll
    for (int mi = 0; mi < 4; mi++) {
        const int arow = moff + mi * 16 + (lane & 15);
        aAddr[mi] = smBase + (uint32_t)(arow * KSH) * 2u + ((lane & 16) ? 16u : 0u);
    }
#pragma unroll
    for (int p = 0; p < 2; p++) {
        const int nrow = noff + p * 16 + ((lane >> 4) & 1) * 8 + (lane & 7);
        bAddr[p] = smBase + (uint32_t)(TILE_HALFS + nrow * KSH) * 2u + ((lane & 8) ? 16u : 0u);
    }

    float acc[4][4][4];
#pragma unroll
    for (int i = 0; i < 4; i++)
#pragma unroll
        for (int j = 0; j < 4; j++)
#pragma unroll
            for (int r = 0; r < 4; r++) acc[i][j][r] = 0.f;

    auto load_chunk = [&](int ch, int s) {
        const int k0 = ch * BKH;
        const uint32_t aBase = smBase + (uint32_t)s * STAGE_BYTES;
        const uint32_t bBase = aBase + TILE_HALFS * 2u;
#pragma unroll
        for (int i = 0; i < 4; i++) {
            const int c   = tid + i * 256;
            const int row = c >> 3;
            const int col = c & 7;                       // 16B (8-half) chunk
            cp_async16(aBase + row * (KSH * 2) + col * 16,
                       A + (size_t)(bm + row) * DMODEL + k0 + col * 8);
            cp_async16(bBase + row * (KSH * 2) + col * 16,
                       B + (size_t)(bn + row) * DMODEL + k0 + col * 8);
        }
        CP_COMMIT();
    };

    load_chunk(0, 0);
    load_chunk(1, 1);

    for (int ch = 0; ch < NCH; ch++) {
        const int s = ch % NSTAGE;
        if (ch + 2 < NCH) CP_WAIT1(); else CP_WAIT0();
        __syncthreads();
        if (ch + 2 < NCH) load_chunk(ch + 2, (ch + 2) % NSTAGE);

        const uint32_t soff = (uint32_t)s * STAGE_BYTES;
#pragma unroll
        for (int ks = 0; ks < 4; ks++) {                 // k16 per step = 32B
            const uint32_t kOff = soff + ks * 32u;
            uint32_t af[4][4], bf[2][4];
#pragma unroll
            for (int mi = 0; mi < 4; mi++) ldsm_x4(af[mi], aAddr[mi] + kOff);
#pragma unroll
            for (int p = 0; p < 2; p++)    ldsm_x4(bf[p],  bAddr[p] + kOff);
#pragma unroll
            for (int mi = 0; mi < 4; mi++)
#pragma unroll
                for (int ni = 0; ni < 4; ni++)
                    mma16x8x16(acc[mi][ni], af[mi], &bf[ni >> 1][(ni & 1) * 2]);
        }
    }
    __syncthreads();

    // epilogue
    if (Ch) {
#pragma unroll
        for (int mi = 0; mi < 4; mi++)
#pragma unroll
            for (int ni = 0; ni < 4; ni++) {
                const int row0 = bm + moff + mi * 16 + gid;
                const int col0 = bn + noff + ni * 8 + 2 * tig;
                __half2* p0 = (__half2*)&Ch[(size_t)row0 * DMODEL + col0];
                __half2* p1 = (__half2*)&Ch[(size_t)(row0 + 8) * DMODEL + col0];
                *p0 = __floats2half2_rn(acc[mi][ni][0], acc[mi][ni][1]);
                *p1 = __floats2half2_rn(acc[mi][ni][2], acc[mi][ni][3]);
            }
    } else {
#pragma unroll
        for (int mi = 0; mi < 4; mi++)
#pragma unroll
            for (int ni = 0; ni < 4; ni++) {
                const int row0 = bm + moff + mi * 16 + gid;
                const int col0 = bn + noff + ni * 8 + 2 * tig;
                *(float2*)&Cf[(size_t)row0 * DMODEL + col0] =
                    make_float2(acc[mi][ni][0], acc[mi][ni][1]);
                *(float2*)&Cf[(size_t)(row0 + 8) * DMODEL + col0] =
                    make_float2(acc[mi][ni][2], acc[mi][ni][3]);
            }
    }
}

// ---------------------------------------------------------------------------
// Merged f32 -> f16 conversion (x + 4 weights in one launch)
// ---------------------------------------------------------------------------
#define XCHUNKS (MROWS * DMODEL / 8)          // 2097152 uint4 chunks
#define WCHUNKS (DMODEL * DMODEL / 8)         // 131072 per weight
#define TOTCHUNKS (XCHUNKS + 4 * WCHUNKS)

__global__ void convert_all_kernel(const float* __restrict__ x,
                                   const float* __restrict__ w0, const float* __restrict__ w1,
                                   const float* __restrict__ w2, const float* __restrict__ w3,
                                   __half* __restrict__ xh,
                                   __half* __restrict__ o0, __half* __restrict__ o1,
                                   __half* __restrict__ o2, __half* __restrict__ o3)
{
    for (int i = blockIdx.x * blockDim.x + threadIdx.x; i < TOTCHUNKS;
         i += gridDim.x * blockDim.x) {
        const float* in;
        __half* out;
        int idx;
        if (i < XCHUNKS) { in = x; out = xh; idx = i; }
        else {
            const int j = i - XCHUNKS;
            const int w = j / WCHUNKS;
            idx = j - w * WCHUNKS;
            in  = (w == 0) ? w0 : (w == 1) ? w1 : (w == 2) ? w2 : w3;
            out = (w == 0) ? o0 : (w == 1) ? o1 : (w == 2) ? o2 : o3;
        }
        float4 v0 = ((const float4*)in)[2 * idx];
        float4 v1 = ((const float4*)in)[2 * idx + 1];
        uint4 o;
        o.x = pack_h2(v0.x, v0.y); o.y = pack_h2(v0.z, v0.w);
        o.z = pack_h2(v1.x, v1.y); o.w = pack_h2(v1.z, v1.w);
        ((uint4*)out)[idx] = o;
    }
}

// ---------------------------------------------------------------------------
// fp16 tensor-core hybrid attention — EXACT R9 version (known good).
// One CTA per (window, head, batch); 8 warps, warp owns 16 query rows.
// 192 keys (64 global + 128 local) in smem. S = Q K^T (m16n8k16), exact
// softmax in registers, P packs directly into fp16 A-frags, O = P V with
// V B-frags via ldmatrix.trans. Smem rows: 64 halfs + 8 pad = 72 halfs.
// ---------------------------------------------------------------------------
#define QS_HALFS (128 * KSH)    // 9216
#define KS_HALFS (192 * KSH)    // 13824
#define VS_HALFS (192 * KSH)
#define ATTN_SMEM_BYTES ((QS_HALFS + KS_HALFS + VS_HALFS) * 2)   // 73728

__global__ __launch_bounds__(256, 1)
void attn_f16(const __half* __restrict__ Q, const __half* __restrict__ K,
              const __half* __restrict__ V, __half* __restrict__ O)
{
    extern __shared__ __half smh[];
    const uint32_t smQ = smem_u32(smh);
    const uint32_t smK = smQ + QS_HALFS * 2u;
    const uint32_t smV = smK + KS_HALFS * 2u;

    const int win  = blockIdx.x;
    const int h    = blockIdx.y;
    const int b    = blockIdx.z;
    const int tid  = threadIdx.x;
    const int wid  = tid >> 5;
    const int lane = tid & 31;
    const int gid  = lane >> 2;   // 0..7
    const int tg   = lane & 3;    // 0..3

    // ---- stage Q (128x64), K (192x64), V (192x64) halfs ----
    const __half* Qg = Q + ((size_t)(b * SEQ + win * WIN)) * DMODEL + h * HDIM;
    for (int i = tid; i < 128 * 8; i += 256) {
        const int row = i >> 3, c8 = i & 7;
        cp_async16(smQ + (uint32_t)(row * KSH) * 2u + c8 * 16,
                   Qg + (size_t)row * DMODEL + c8 * 8);
    }
    for (int i = tid; i < 192 * 8; i += 256) {
        const int row = i >> 3, c8 = i & 7;
        const int tok = (row < 64) ? row : (win * WIN + row - 64);
        const size_t src = ((size_t)(b * SEQ + tok)) * DMODEL + h * HDIM + c8 * 8;
        cp_async16(smK + (uint32_t)(row * KSH) * 2u + c8 * 16, K + src);
        cp_async16(smV + (uint32_t)(row * KSH) * 2u + c8 * 16, V + src);
    }
    CP_COMMIT(); CP_WAIT0();
    __syncthreads();

    // ---- Q A-frags: 4 k16-steps ----
    uint32_t aQ[4][4];
    {
        const uint32_t qb = smQ + (uint32_t)((wid * 16 + (lane & 15)) * KSH) * 2u +
                            ((lane & 16) ? 16u : 0u);
#pragma unroll
        for (int ks = 0; ks < 4; ks++) ldsm_x4(aQ[ks], qb + ks * 32u);
    }

    // ---- S = Q K^T : 24 n8-frags over 192 keys ----
    float sf[24][4];
#pragma unroll
    for (int nf = 0; nf < 24; nf++)
#pragma unroll
        for (int r = 0; r < 4; r++) sf[nf][r] = 0.f;

#pragma unroll
    for (int ks = 0; ks < 4; ks++) {
        uint32_t bf[12][4];
#pragma unroll
        for (int p = 0; p < 12; p++) {
            const int nrow = p * 16 + ((lane >> 4) & 1) * 8 + (lane & 7);
            ldsm_x4(bf[p], smK + (uint32_t)(nrow * KSH) * 2u +
                           ((lane & 8) ? 16u : 0u) + ks * 32u);
        }
#pragma unroll
        for (int p = 0; p < 12; p++) {
            mma16x8x16(sf[2 * p],     aQ[ks], &bf[p][0]);
            mma16x8x16(sf[2 * p + 1], aQ[ks], &bf[p][2]);
        }
    }

    // ---- exact softmax (rows rA = gid, rB = gid+8; scale 1/8 in exp arg) ----
    float mA = -1e30f, mB = -1e30f;
#pragma unroll
    for (int nf = 0; nf < 24; nf++) {
        mA = fmaxf(mA, fmaxf(sf[nf][0], sf[nf][1]));
        mB = fmaxf(mB, fmaxf(sf[nf][2], sf[nf][3]));
    }
    mA = fmaxf(mA, __shfl_xor_sync(0xffffffffu, mA, 1));
    mA = fmaxf(mA, __shfl_xor_sync(0xffffffffu, mA, 2));
    mB = fmaxf(mB, __shfl_xor_sync(0xffffffffu, mB, 1));
    mB = fmaxf(mB, __shfl_xor_sync(0xffffffffu, mB, 2));

    float lA = 0.f, lB = 0.f;
#pragma unroll
    for (int nf = 0; nf < 24; nf++) {
        float p0 = __expf((sf[nf][0] - mA) * 0.125f);
        float p1 = __expf((sf[nf][1] - mA) * 0.125f);
        float p2 = __expf((sf[nf][2] - mB) * 0.125f);
        float p3 = __expf((sf[nf][3] - mB) * 0.125f);
        sf[nf][0] = p0; sf[nf][1] = p1; sf[nf][2] = p2; sf[nf][3] = p3;
        lA += p0 + p1; lB += p2 + p3;
    }
    lA += __shfl_xor_sync(0xffffffffu, lA, 1);
    lA += __shfl_xor_sync(0xffffffffu, lA, 2);
    lB += __shfl_xor_sync(0xffffffffu, lB, 1);
    lB += __shfl_xor_sync(0xffffffffu, lB, 2);

    // ---- O = P V : 12 k16-steps, 8 n8-frags (64 dims) ----
    float oc[8][4];
#pragma unroll
    for (int nf = 0; nf < 8; nf++)
#pragma unroll
        for (int r = 0; r < 4; r++) oc[nf][r] = 0.f;

#pragma unroll
    for (int j = 0; j < 12; j++) {
        // P A-frag for keys 16j..16j+15: identity relayout from C-frags
        uint32_t a[4];
        a[0] = pack_h2(sf[2 * j][0],     sf[2 * j][1]);
        a[1] = pack_h2(sf[2 * j][2],     sf[2 * j][3]);
        a[2] = pack_h2(sf[2 * j + 1][0], sf[2 * j + 1][1]);
        a[3] = pack_h2(sf[2 * j + 1][2], sf[2 * j + 1][3]);

        // V B-frags via ldmatrix.trans: rows = keys, cols = dims
        const uint32_t vb = smV + (uint32_t)((j * 16 + ((lane >> 3) & 1) * 8 + (lane & 7)) * KSH) * 2u +
                            ((lane & 16) ? 16u : 0u);
#pragma unroll
        for (int t = 0; t < 2; t++) {        // dim groups 32t .. 32t+31
            uint32_t bv[4];
            ldsm_x4t(bv, vb + t * 64u);
            mma16x8x16(oc[4 * t],     a, &bv[0]);
            mma16x8x16(oc[4 * t + 1], a, &bv[2]);
            uint32_t bv2[4];
            ldsm_x4t(bv2, vb + t * 64u + 32u);
            mma16x8x16(oc[4 * t + 2], a, &bv2[0]);
            mma16x8x16(oc[4 * t + 3], a, &bv2[2]);
        }
    }

    // ---- epilogue: divide by l, write half ----
    const float invA = 1.f / lA, invB = 1.f / lB;
    const int qrow = win * WIN + wid * 16 + gid;
    __half* outA = O + ((size_t)(b * SEQ + qrow)) * DMODEL + h * HDIM;
    __half* outB = outA + 8 * DMODEL;
#pragma unroll
    for (int nf = 0; nf < 8; nf++) {
        const int col = nf * 8 + 2 * tg;
        *(__half2*)(outA + col) = __floats2half2_rn(oc[nf][0] * invA, oc[nf][1] * invA);
        *(__half2*)(outB + col) = __floats2half2_rn(oc[nf][2] * invB, oc[nf][3] * invB);
    }
}

// ---------------------------------------------------------------------------
extern "C" void kernel_launch(void* const* d_in, const int* in_sizes, int n_in,
                              void* d_out, int out_size)
{
    const float* x  = (const float*)d_in[0];
    const float* Wq = (const float*)d_in[1];
    const float* Wk = (const float*)d_in[2];
    const float* Wv = (const float*)d_in[3];
    const float* Wo = (const float*)d_in[4];
    float* out = (float*)d_out;

    __half *xh, *qh, *kh, *vh, *ah, *wqh, *wkh, *wvh, *woh;
    cudaGetSymbolAddress((void**)&xh,  g_xh);
    cudaGetSymbolAddress((void**)&qh,  g_qh);
    cudaGetSymbolAddress((void**)&kh,  g_kh);
    cudaGetSymbolAddress((void**)&vh,  g_vh);
    cudaGetSymbolAddress((void**)&ah,  g_ah);
    cudaGetSymbolAddress((void**)&wqh, g_wqh);
    cudaGetSymbolAddress((void**)&wkh, g_wkh);
    cudaGetSymbolAddress((void**)&wvh, g_wvh);
    cudaGetSymbolAddress((void**)&woh, g_woh);

    cudaFuncSetAttribute(gemm_f16, cudaFuncAttributeMaxDynamicSharedMemorySize,
                         GEMM_SMEM_BYTES);
    cudaFuncSetAttribute(attn_f16, cudaFuncAttributeMaxDynamicSharedMemorySize,
                         ATTN_SMEM_BYTES);

    // merged f32 -> f16 prep (one launch)
    convert_all_kernel<<<2048, 256>>>(x, Wq, Wk, Wv, Wo, xh, wqh, wkh, wvh, woh);

    // fused QKV projection (half outputs feed attention)
    dim3 gqkv(DMODEL / BN, MROWS / BM, 3);   // (8, 128, 3)
    gemm_f16<<<gqkv, 256, GEMM_SMEM_BYTES>>>(xh, wqh, wkh, wvh,
                                             nullptr, qh, kh, vh);

    dim3 ga(NWIN, NHEADS, BATCH);            // (64, 16, 2)
    attn_f16<<<ga, 256, ATTN_SMEM_BYTES>>>(qh, kh, vh, ah);

    // output projection (float output)
    dim3 go(DMODEL / BN, MROWS / BM, 1);
    gemm_f16<<<go, 256, GEMM_SMEM_BYTES>>>(ah, woh, woh, woh,
                                           out, nullptr, nullptr, nullptr);
}